// round 1
// baseline (speedup 1.0000x reference)
#include <cuda_runtime.h>
#include <math.h>

#define N_NODES 50000
#define D 128

// scratch (device globals -- no allocation allowed)
__device__ float g_h0[N_NODES * D];
__device__ float g_h1[N_NODES * D];
__device__ float g_hagg[N_NODES * D];
__device__ float g_deg[N_NODES];

// ---------------------------------------------------------------------------
// degree
// ---------------------------------------------------------------------------
__global__ void k_zero_deg() {
    int i = blockIdx.x * blockDim.x + threadIdx.x;
    if (i < N_NODES) g_deg[i] = 0.0f;
}

__global__ void k_count_deg(const int* __restrict__ dst, int etot) {
    int i = blockIdx.x * blockDim.x + threadIdx.x;
    if (i < etot) atomicAdd(&g_deg[dst[i]], 1.0f);
}

// ---------------------------------------------------------------------------
// h_agg = -h   (so the self-loop edge cancels: final = sum_in - h)
// ---------------------------------------------------------------------------
__global__ void k_init_hagg(const float* __restrict__ h) {
    int i = blockIdx.x * blockDim.x + threadIdx.x;
    if (i < N_NODES * D) g_hagg[i] = -h[i];
}

// ---------------------------------------------------------------------------
// scatter: one warp per edge, float4 gather + 4 scalar fp32 atomics per lane
// ---------------------------------------------------------------------------
__global__ void k_scatter(const float* __restrict__ h,
                          const int* __restrict__ src,
                          const int* __restrict__ dst, int etot) {
    int gid  = blockIdx.x * blockDim.x + threadIdx.x;
    int wid  = gid >> 5;
    int lane = threadIdx.x & 31;
    if (wid >= etot) return;
    int s = __ldg(src + wid);
    int t = __ldg(dst + wid);
    float4 v = ((const float4*)(h + (size_t)s * D))[lane];
    float* o = g_hagg + (size_t)t * D + lane * 4;
    atomicAdd(o + 0, v.x);
    atomicAdd(o + 1, v.y);
    atomicAdd(o + 2, v.z);
    atomicAdd(o + 3, v.w);
}

// ---------------------------------------------------------------------------
// mix: h0 = node_emb[n+1] + leaky_relu(content @ proj_W^T + proj_b, 0.1)
// Tiled fp32 GEMM: block = 64 nodes x 128 out dims, 256 threads, KT=32
// thread (ty,tx): nodes ty+16i (i<4), dims tx+16j (j<8)
// ---------------------------------------------------------------------------
__global__ __launch_bounds__(256) void k_mix(const float* __restrict__ content,
                                             const float* __restrict__ pW,
                                             const float* __restrict__ pb,
                                             const float* __restrict__ emb,
                                             float* __restrict__ out) {
    const int K = 300;
    __shared__ float Xs[64][33];
    __shared__ float Ws[32][129];
    int tid = threadIdx.x;
    int tx = tid & 15, ty = tid >> 4;
    int nb = blockIdx.x * 64;

    float acc[4][8];
#pragma unroll
    for (int i = 0; i < 4; i++)
#pragma unroll
        for (int j = 0; j < 8; j++) acc[i][j] = 0.0f;

    for (int kt = 0; kt < K; kt += 32) {
#pragma unroll
        for (int it = 0; it < 8; it++) {
            int i = tid + it * 256;
            int r = i >> 5, c = i & 31;
            int n = nb + r, k = kt + c;
            float v = 0.0f;
            if (n < N_NODES && k < K) v = content[(size_t)n * K + k];
            Xs[r][c] = v;
        }
#pragma unroll
        for (int it = 0; it < 16; it++) {
            int i = tid + it * 256;
            int k = i & 31, d = i >> 5;
            int kk = kt + k;
            Ws[k][d] = (kk < K) ? pW[(size_t)d * K + kk] : 0.0f;
        }
        __syncthreads();
#pragma unroll
        for (int k = 0; k < 32; k++) {
            float xr[4], wr[8];
#pragma unroll
            for (int i = 0; i < 4; i++) xr[i] = Xs[ty + 16 * i][k];
#pragma unroll
            for (int j = 0; j < 8; j++) wr[j] = Ws[k][tx + 16 * j];
#pragma unroll
            for (int i = 0; i < 4; i++)
#pragma unroll
                for (int j = 0; j < 8; j++) acc[i][j] += xr[i] * wr[j];
        }
        __syncthreads();
    }

#pragma unroll
    for (int i = 0; i < 4; i++) {
        int n = nb + ty + 16 * i;
        if (n >= N_NODES) continue;
#pragma unroll
        for (int j = 0; j < 8; j++) {
            int d = tx + 16 * j;
            float v = acc[i][j] + pb[d];
            v = (v > 0.0f) ? v : 0.1f * v;
            out[(size_t)n * D + d] = v + emb[(size_t)(n + 1) * D + d];
        }
    }
}

// ---------------------------------------------------------------------------
// SAGE layer: X = [h, (hagg)*inv_w] (hagg already holds sum - h)
// out = normalize( (use_act ? lrelu : id)(X @ W^T + b) )
// Same tiling as k_mix with K=256; epilogue does row-norm via shared.
// ---------------------------------------------------------------------------
__global__ __launch_bounds__(256) void k_sage(const float* __restrict__ h,
                                              const float* __restrict__ W,
                                              const float* __restrict__ b,
                                              float* __restrict__ out,
                                              int use_act) {
    const int K = 256;
    __shared__ float sbuf[64 * 129];  // 33 KB, unioned
    float(*Xs)[33] = (float(*)[33])sbuf;                // 64*33 = 2112 floats
    float(*Ws)[129] = (float(*)[129])(sbuf + 64 * 33);  // 32*129 = 4128 floats
    float(*Ys)[129] = (float(*)[129])sbuf;              // epilogue alias

    int tid = threadIdx.x;
    int tx = tid & 15, ty = tid >> 4;
    int nb = blockIdx.x * 64;

    float acc[4][8];
#pragma unroll
    for (int i = 0; i < 4; i++)
#pragma unroll
        for (int j = 0; j < 8; j++) acc[i][j] = 0.0f;

    for (int kt = 0; kt < K; kt += 32) {
        bool agg = (kt >= 128);
        const float* X = agg ? g_hagg : h;
        int kbase = agg ? (kt - 128) : kt;
#pragma unroll
        for (int it = 0; it < 8; it++) {
            int i = tid + it * 256;
            int r = i >> 5, c = i & 31;
            int n = nb + r;
            float v = 0.0f;
            if (n < N_NODES) {
                v = X[(size_t)n * D + kbase + c];
                if (agg) {
                    float w = g_deg[n];
                    v *= 1.0f / fmaxf(w - 1.0f, 1.0f);
                }
            }
            Xs[r][c] = v;
        }
#pragma unroll
        for (int it = 0; it < 16; it++) {
            int i = tid + it * 256;
            int k = i & 31, d = i >> 5;
            Ws[k][d] = W[(size_t)d * K + kt + k];
        }
        __syncthreads();
#pragma unroll
        for (int k = 0; k < 32; k++) {
            float xr[4], wr[8];
#pragma unroll
            for (int i = 0; i < 4; i++) xr[i] = Xs[ty + 16 * i][k];
#pragma unroll
            for (int j = 0; j < 8; j++) wr[j] = Ws[k][tx + 16 * j];
#pragma unroll
            for (int i = 0; i < 4; i++)
#pragma unroll
                for (int j = 0; j < 8; j++) acc[i][j] += xr[i] * wr[j];
        }
        __syncthreads();
    }

    // epilogue: bias + optional leaky_relu, stash to shared for row-norm
#pragma unroll
    for (int i = 0; i < 4; i++) {
#pragma unroll
        for (int j = 0; j < 8; j++) {
            int d = tx + 16 * j;
            float v = acc[i][j] + b[d];
            if (use_act) v = (v > 0.0f) ? v : 0.1f * v;
            Ys[ty + 16 * i][d] = v;
        }
    }
    __syncthreads();

    // row norm: 4 threads per node
    int node = tid >> 2, part = tid & 3;
    int n = nb + node;
    float s = 0.0f;
#pragma unroll
    for (int c = 0; c < 32; c++) {
        float v = Ys[node][part * 32 + c];
        s += v * v;
    }
    s += __shfl_xor_sync(0xFFFFFFFFu, s, 1);
    s += __shfl_xor_sync(0xFFFFFFFFu, s, 2);
    float inv = 1.0f / fmaxf(sqrtf(s), 1e-6f);
    if (n < N_NODES) {
#pragma unroll
        for (int c = 0; c < 32; c++)
            out[(size_t)n * D + part * 32 + c] = Ys[node][part * 32 + c] * inv;
    }
}

// ---------------------------------------------------------------------------
extern "C" void kernel_launch(void* const* d_in, const int* in_sizes, int n_in,
                              void* d_out, int out_size) {
    const float* node_emb = (const float*)d_in[0];
    const float* content  = (const float*)d_in[1];
    const float* proj_W   = (const float*)d_in[2];
    const float* proj_b   = (const float*)d_in[3];
    const float* W1       = (const float*)d_in[4];
    const float* b1       = (const float*)d_in[5];
    const float* W2       = (const float*)d_in[6];
    const float* b2       = (const float*)d_in[7];
    const int*   esrc     = (const int*)d_in[8];
    const int*   edst     = (const int*)d_in[9];
    int etot = in_sizes[8];
    float* out = (float*)d_out;

    float *h0, *h1;
    cudaGetSymbolAddress((void**)&h0, g_h0);
    cudaGetSymbolAddress((void**)&h1, g_h1);

    int nd_blocks = (N_NODES * D + 255) / 256;
    int n_blocks  = (N_NODES + 255) / 256;
    int e_blocks  = (etot + 255) / 256;
    int sc_blocks = (etot + 7) / 8;          // 1 warp per edge, 8 warps/block
    int gemm_blocks = (N_NODES + 63) / 64;

    // degree (same graph both layers)
    k_zero_deg<<<n_blocks, 256>>>();
    k_count_deg<<<e_blocks, 256>>>(edst, etot);

    // h0 = emb + lrelu(content @ projW^T + b)
    k_mix<<<gemm_blocks, 256>>>(content, proj_W, proj_b, node_emb, h0);

    // layer 1
    k_init_hagg<<<nd_blocks, 256>>>(h0);
    k_scatter<<<sc_blocks, 256>>>(h0, esrc, edst, etot);
    k_sage<<<gemm_blocks, 256>>>(h0, W1, b1, h1, 1);

    // layer 2
    k_init_hagg<<<nd_blocks, 256>>>(h1);
    k_scatter<<<sc_blocks, 256>>>(h1, esrc, edst, etot);
    k_sage<<<gemm_blocks, 256>>>(h1, W2, b2, out, 0);
}

// round 2
// speedup vs baseline: 1.7702x; 1.7702x over previous
#include <cuda_runtime.h>
#include <math.h>

#define N_NODES 50000
#define D 128

// scratch (device globals -- no allocation allowed)
__device__ float g_h0[N_NODES * D];
__device__ float g_h1[N_NODES * D];
__device__ float g_hagg[N_NODES * D];
__device__ float g_deg[N_NODES];

// ---------------------------------------------------------------------------
// degree
// ---------------------------------------------------------------------------
__global__ void k_zero_deg() {
    int i = blockIdx.x * blockDim.x + threadIdx.x;
    if (i < N_NODES) g_deg[i] = 0.0f;
}

__global__ void k_count_deg(const int* __restrict__ dst, int etot) {
    int i = blockIdx.x * blockDim.x + threadIdx.x;
    if (i < etot) atomicAdd(&g_deg[dst[i]], 1.0f);
}

// ---------------------------------------------------------------------------
// h_agg = -h   (so the self-loop edge cancels: final = sum_in - h)
// ---------------------------------------------------------------------------
__global__ void k_init_hagg(const float* __restrict__ h) {
    int i = blockIdx.x * blockDim.x + threadIdx.x;
    if (i < N_NODES * D) g_hagg[i] = -h[i];
}

// ---------------------------------------------------------------------------
// scatter: one warp per edge, float4 gather + one red.global.add.v4.f32/lane
// ---------------------------------------------------------------------------
__global__ void k_scatter(const float* __restrict__ h,
                          const int* __restrict__ src,
                          const int* __restrict__ dst, int etot) {
    int gid  = blockIdx.x * blockDim.x + threadIdx.x;
    int wid  = gid >> 5;
    int lane = threadIdx.x & 31;
    if (wid >= etot) return;
    int s = __ldg(src + wid);
    int t = __ldg(dst + wid);
    float4 v = ((const float4*)(h + (size_t)s * D))[lane];
    float4* o = ((float4*)(g_hagg + (size_t)t * D)) + lane;
    asm volatile("red.global.add.v4.f32 [%0], {%1,%2,%3,%4};"
                 :: "l"(o), "f"(v.x), "f"(v.y), "f"(v.z), "f"(v.w)
                 : "memory");
}

// ---------------------------------------------------------------------------
// 128x128x16 SGEMM tile machinery (256 threads, 8x8 per thread)
// As/Bs stored transposed: As[k][m], Bs[k][n]; inner loop all LDS.128.
// ---------------------------------------------------------------------------

// mix: h0 = node_emb[n+1] + leaky_relu(content @ proj_W^T + proj_b, 0.1)
__global__ __launch_bounds__(256) void k_mix(const float* __restrict__ content,
                                             const float* __restrict__ pW,
                                             const float* __restrict__ pb,
                                             const float* __restrict__ emb,
                                             float* __restrict__ out) {
    const int K = 300;
    __shared__ float As[16][132];
    __shared__ float Bs[16][132];
    int tid = threadIdx.x;
    int tx = tid & 15, ty = tid >> 4;
    int nb = blockIdx.x * 128;
    int lrow = tid >> 1;           // 0..127
    int lc0  = (tid & 1) * 8;      // 0 or 8

    float acc[8][8];
#pragma unroll
    for (int i = 0; i < 8; i++)
#pragma unroll
        for (int j = 0; j < 8; j++) acc[i][j] = 0.0f;

    for (int kt = 0; kt < K; kt += 16) {
        // --- A tile: content[nb+lrow][kt+lc0 .. +7]
        {
            int n = nb + lrow;
            float v[8];
            if (kt + 16 <= K && n < N_NODES) {
                const float* base = content + (size_t)n * K + kt + lc0;
                *(float4*)&v[0] = *(const float4*)(base);
                *(float4*)&v[4] = *(const float4*)(base + 4);
            } else {
#pragma unroll
                for (int j = 0; j < 8; j++) {
                    int kk = kt + lc0 + j;
                    v[j] = (n < N_NODES && kk < K) ? content[(size_t)n * K + kk] : 0.0f;
                }
            }
#pragma unroll
            for (int j = 0; j < 8; j++) As[lc0 + j][lrow] = v[j];
        }
        // --- B tile: Bs[k][d] = pW[d][kt+k], d = lrow
        {
            float v[8];
            if (kt + 16 <= K) {
                const float* base = pW + (size_t)lrow * K + kt + lc0;
                *(float4*)&v[0] = *(const float4*)(base);
                *(float4*)&v[4] = *(const float4*)(base + 4);
            } else {
#pragma unroll
                for (int j = 0; j < 8; j++) {
                    int kk = kt + lc0 + j;
                    v[j] = (kk < K) ? pW[(size_t)lrow * K + kk] : 0.0f;
                }
            }
#pragma unroll
            for (int j = 0; j < 8; j++) Bs[lc0 + j][lrow] = v[j];
        }
        __syncthreads();
#pragma unroll
        for (int k = 0; k < 16; k++) {
            float a[8], b[8];
            *(float4*)&a[0] = *(const float4*)&As[k][ty * 8];
            *(float4*)&a[4] = *(const float4*)&As[k][ty * 8 + 4];
            *(float4*)&b[0] = *(const float4*)&Bs[k][tx * 8];
            *(float4*)&b[4] = *(const float4*)&Bs[k][tx * 8 + 4];
#pragma unroll
            for (int i = 0; i < 8; i++)
#pragma unroll
                for (int j = 0; j < 8; j++) acc[i][j] += a[i] * b[j];
        }
        __syncthreads();
    }

    // epilogue: bias + lrelu + emb add
    float bj[8];
    *(float4*)&bj[0] = *(const float4*)(pb + tx * 8);
    *(float4*)&bj[4] = *(const float4*)(pb + tx * 8 + 4);
#pragma unroll
    for (int i = 0; i < 8; i++) {
        int n = nb + ty * 8 + i;
        if (n >= N_NODES) continue;
        float e[8];
        *(float4*)&e[0] = *(const float4*)(emb + (size_t)(n + 1) * D + tx * 8);
        *(float4*)&e[4] = *(const float4*)(emb + (size_t)(n + 1) * D + tx * 8 + 4);
        float o[8];
#pragma unroll
        for (int j = 0; j < 8; j++) {
            float v = acc[i][j] + bj[j];
            v = (v > 0.0f) ? v : 0.1f * v;
            o[j] = v + e[j];
        }
        *(float4*)(out + (size_t)n * D + tx * 8)     = *(float4*)&o[0];
        *(float4*)(out + (size_t)n * D + tx * 8 + 4) = *(float4*)&o[4];
    }
}

// SAGE layer: X = [h, (sum_in - h)*inv_w]; out = normalize(act(X @ W^T + b))
__global__ __launch_bounds__(256) void k_sage(const float* __restrict__ h,
                                              const float* __restrict__ W,
                                              const float* __restrict__ bias,
                                              float* __restrict__ out,
                                              int use_act) {
    __shared__ float As[16][132];
    __shared__ float Bs[16][132];
    int tid = threadIdx.x;
    int tx = tid & 15, ty = tid >> 4;
    int nb = blockIdx.x * 128;
    int lrow = tid >> 1;
    int lc0  = (tid & 1) * 8;

    float acc[8][8];
#pragma unroll
    for (int i = 0; i < 8; i++)
#pragma unroll
        for (int j = 0; j < 8; j++) acc[i][j] = 0.0f;

    for (int kt = 0; kt < 256; kt += 16) {
        // --- A tile
        {
            int n = nb + lrow;
            float v[8];
            bool agg = (kt >= 128);
            if (n < N_NODES) {
                const float* base = agg
                    ? (g_hagg + (size_t)n * D + (kt - 128) + lc0)
                    : (h + (size_t)n * D + kt + lc0);
                *(float4*)&v[0] = *(const float4*)(base);
                *(float4*)&v[4] = *(const float4*)(base + 4);
                if (agg) {
                    float s = 1.0f / fmaxf(g_deg[n] - 1.0f, 1.0f);
#pragma unroll
                    for (int j = 0; j < 8; j++) v[j] *= s;
                }
            } else {
#pragma unroll
                for (int j = 0; j < 8; j++) v[j] = 0.0f;
            }
#pragma unroll
            for (int j = 0; j < 8; j++) As[lc0 + j][lrow] = v[j];
        }
        // --- B tile: Bs[k][d] = W[d][kt+k], d = lrow
        {
            const float* base = W + (size_t)lrow * 256 + kt + lc0;
            float v[8];
            *(float4*)&v[0] = *(const float4*)(base);
            *(float4*)&v[4] = *(const float4*)(base + 4);
#pragma unroll
            for (int j = 0; j < 8; j++) Bs[lc0 + j][lrow] = v[j];
        }
        __syncthreads();
#pragma unroll
        for (int k = 0; k < 16; k++) {
            float a[8], b[8];
            *(float4*)&a[0] = *(const float4*)&As[k][ty * 8];
            *(float4*)&a[4] = *(const float4*)&As[k][ty * 8 + 4];
            *(float4*)&b[0] = *(const float4*)&Bs[k][tx * 8];
            *(float4*)&b[4] = *(const float4*)&Bs[k][tx * 8 + 4];
#pragma unroll
            for (int i = 0; i < 8; i++)
#pragma unroll
                for (int j = 0; j < 8; j++) acc[i][j] += a[i] * b[j];
        }
        __syncthreads();
    }

    // epilogue: bias + optional lrelu + row L2 norm (16 threads own a row)
    float bj[8];
    *(float4*)&bj[0] = *(const float4*)(bias + tx * 8);
    *(float4*)&bj[4] = *(const float4*)(bias + tx * 8 + 4);
    float inv[8];
#pragma unroll
    for (int i = 0; i < 8; i++) {
        float s = 0.0f;
#pragma unroll
        for (int j = 0; j < 8; j++) {
            float v = acc[i][j] + bj[j];
            if (use_act) v = (v > 0.0f) ? v : 0.1f * v;
            acc[i][j] = v;
            s += v * v;
        }
        s += __shfl_xor_sync(0xFFFFFFFFu, s, 1);
        s += __shfl_xor_sync(0xFFFFFFFFu, s, 2);
        s += __shfl_xor_sync(0xFFFFFFFFu, s, 4);
        s += __shfl_xor_sync(0xFFFFFFFFu, s, 8);
        inv[i] = 1.0f / fmaxf(sqrtf(s), 1e-6f);
    }
#pragma unroll
    for (int i = 0; i < 8; i++) {
        int n = nb + ty * 8 + i;
        if (n >= N_NODES) continue;
        float o[8];
#pragma unroll
        for (int j = 0; j < 8; j++) o[j] = acc[i][j] * inv[i];
        *(float4*)(out + (size_t)n * D + tx * 8)     = *(float4*)&o[0];
        *(float4*)(out + (size_t)n * D + tx * 8 + 4) = *(float4*)&o[4];
    }
}

// ---------------------------------------------------------------------------
extern "C" void kernel_launch(void* const* d_in, const int* in_sizes, int n_in,
                              void* d_out, int out_size) {
    const float* node_emb = (const float*)d_in[0];
    const float* content  = (const float*)d_in[1];
    const float* proj_W   = (const float*)d_in[2];
    const float* proj_b   = (const float*)d_in[3];
    const float* W1       = (const float*)d_in[4];
    const float* b1       = (const float*)d_in[5];
    const float* W2       = (const float*)d_in[6];
    const float* b2       = (const float*)d_in[7];
    const int*   esrc     = (const int*)d_in[8];
    const int*   edst     = (const int*)d_in[9];
    int etot = in_sizes[8];
    float* out = (float*)d_out;

    float *h0, *h1;
    cudaGetSymbolAddress((void**)&h0, g_h0);
    cudaGetSymbolAddress((void**)&h1, g_h1);

    int nd_blocks = (N_NODES * D + 255) / 256;
    int n_blocks  = (N_NODES + 255) / 256;
    int e_blocks  = (etot + 255) / 256;
    int sc_blocks = (etot + 7) / 8;            // 1 warp per edge, 8 warps/block
    int gemm_blocks = (N_NODES + 127) / 128;

    // degree (same graph both layers)
    k_zero_deg<<<n_blocks, 256>>>();
    k_count_deg<<<e_blocks, 256>>>(edst, etot);

    // h0 = emb + lrelu(content @ projW^T + b)
    k_mix<<<gemm_blocks, 256>>>(content, proj_W, proj_b, node_emb, h0);

    // layer 1
    k_init_hagg<<<nd_blocks, 256>>>(h0);
    k_scatter<<<sc_blocks, 256>>>(h0, esrc, edst, etot);
    k_sage<<<gemm_blocks, 256>>>(h0, W1, b1, h1, 1);

    // layer 2
    k_init_hagg<<<nd_blocks, 256>>>(h1);
    k_scatter<<<sc_blocks, 256>>>(h1, esrc, edst, etot);
    k_sage<<<gemm_blocks, 256>>>(h1, W2, b2, out, 0);
}

// round 4
// speedup vs baseline: 2.2374x; 1.2639x over previous
#include <cuda_runtime.h>
#include <math.h>
#include <stdint.h>

#define N_NODES 50000
#define D 128
#define E_MAX 1700000

// scratch (device globals -- no allocation allowed)
__device__ float g_h0[N_NODES * D];
__device__ float g_h1[N_NODES * D];
__device__ float g_hagg[N_NODES * D];
__device__ float g_invdeg[N_NODES];
__device__ int   g_cnt[N_NODES];
__device__ int   g_off[N_NODES + 1];
__device__ int   g_csrc[E_MAX];

// ---------------------------------------------------------------------------
// CSR build: histogram -> scan -> fill
// ---------------------------------------------------------------------------
__global__ void k_zero_cnt() {
    int i = blockIdx.x * blockDim.x + threadIdx.x;
    if (i < N_NODES) g_cnt[i] = 0;
}

__global__ void k_hist(const int* __restrict__ dst, int etot) {
    int i = blockIdx.x * blockDim.x + threadIdx.x;
    if (i < etot) atomicAdd(&g_cnt[dst[i]], 1);
}

#define SCAN_T 1024
__global__ __launch_bounds__(SCAN_T) void k_scan(int etot) {
    __shared__ int sm[SCAN_T];
    int t = threadIdx.x;
    const int per = (N_NODES + SCAN_T - 1) / SCAN_T;  // 49
    int b = t * per;
    int e = min(b + per, N_NODES);
    int s = 0;
    for (int i = b; i < e; i++) s += g_cnt[i];
    sm[t] = s;
    __syncthreads();
    for (int d = 1; d < SCAN_T; d <<= 1) {
        int v = (t >= d) ? sm[t - d] : 0;
        __syncthreads();
        sm[t] += v;
        __syncthreads();
    }
    int run = (t == 0) ? 0 : sm[t - 1];
    for (int i = b; i < e; i++) {
        int c = g_cnt[i];
        g_off[i] = run;
        g_cnt[i] = run;  // becomes fill cursor
        g_invdeg[i] = 1.0f / fmaxf((float)c - 1.0f, 1.0f);
        run += c;
    }
    if (t == SCAN_T - 1) g_off[N_NODES] = etot;
}

__global__ void k_fill(const int* __restrict__ src, const int* __restrict__ dst,
                       int etot) {
    int i = blockIdx.x * blockDim.x + threadIdx.x;
    if (i < etot) {
        int slot = atomicAdd(&g_cnt[dst[i]], 1);
        g_csrc[slot] = src[i];
    }
}

// ---------------------------------------------------------------------------
// gather: one warp per node.  hagg[n] = (sum_{s in in(n)} h[s] - h[n]) * invdeg
// (edge list includes the self-loop, so subtracting h[n] removes it)
// ---------------------------------------------------------------------------
__global__ __launch_bounds__(256) void k_gather(const float* __restrict__ h) {
    int warp = (blockIdx.x * blockDim.x + threadIdx.x) >> 5;
    int lane = threadIdx.x & 31;
    if (warp >= N_NODES) return;
    int beg = g_off[warp], end = g_off[warp + 1];

    float4 self = ((const float4*)(h + (size_t)warp * D))[lane];
    float ax = -self.x, ay = -self.y, az = -self.z, aw = -self.w;

    int e = beg;
    for (; e + 4 <= end; e += 4) {
        int s0 = __ldg(&g_csrc[e + 0]);
        int s1 = __ldg(&g_csrc[e + 1]);
        int s2 = __ldg(&g_csrc[e + 2]);
        int s3 = __ldg(&g_csrc[e + 3]);
        float4 v0 = ((const float4*)(h + (size_t)s0 * D))[lane];
        float4 v1 = ((const float4*)(h + (size_t)s1 * D))[lane];
        float4 v2 = ((const float4*)(h + (size_t)s2 * D))[lane];
        float4 v3 = ((const float4*)(h + (size_t)s3 * D))[lane];
        ax += (v0.x + v1.x) + (v2.x + v3.x);
        ay += (v0.y + v1.y) + (v2.y + v3.y);
        az += (v0.z + v1.z) + (v2.z + v3.z);
        aw += (v0.w + v1.w) + (v2.w + v3.w);
    }
    for (; e < end; e++) {
        int s0 = __ldg(&g_csrc[e]);
        float4 v0 = ((const float4*)(h + (size_t)s0 * D))[lane];
        ax += v0.x; ay += v0.y; az += v0.z; aw += v0.w;
    }
    float sc = g_invdeg[warp];
    float4 o = make_float4(ax * sc, ay * sc, az * sc, aw * sc);
    ((float4*)(g_hagg + (size_t)warp * D))[lane] = o;
}

// ---------------------------------------------------------------------------
// 128x128x16 SGEMM tile machinery (256 threads, 8x8 per thread)
// As/Bs stored transposed: As[k][m], Bs[k][n]; inner loop all LDS.128.
// ---------------------------------------------------------------------------

// mix: h0 = node_emb[n+1] + leaky_relu(content @ proj_W^T + proj_b, 0.1)
__global__ __launch_bounds__(256) void k_mix(const float* __restrict__ content,
                                             const float* __restrict__ pW,
                                             const float* __restrict__ pb,
                                             const float* __restrict__ emb,
                                             float* __restrict__ out) {
    const int K = 300;
    __shared__ float As[16][132];
    __shared__ float Bs[16][132];
    int tid = threadIdx.x;
    int tx = tid & 15, ty = tid >> 4;
    int nb = blockIdx.x * 128;
    int lrow = tid >> 1;           // 0..127
    int lc0  = (tid & 1) * 8;      // 0 or 8

    float acc[8][8];
#pragma unroll
    for (int i = 0; i < 8; i++)
#pragma unroll
        for (int j = 0; j < 8; j++) acc[i][j] = 0.0f;

    for (int kt = 0; kt < K; kt += 16) {
        // --- A tile: content[nb+lrow][kt+lc0 .. +7]
        {
            int n = nb + lrow;
            float v[8];
            if (kt + 16 <= K && n < N_NODES) {
                const float* base = content + (size_t)n * K + kt + lc0;
                *(float4*)&v[0] = *(const float4*)(base);
                *(float4*)&v[4] = *(const float4*)(base + 4);
            } else {
#pragma unroll
                for (int j = 0; j < 8; j++) {
                    int kk = kt + lc0 + j;
                    v[j] = (n < N_NODES && kk < K) ? content[(size_t)n * K + kk] : 0.0f;
                }
            }
#pragma unroll
            for (int j = 0; j < 8; j++) As[lc0 + j][lrow] = v[j];
        }
        // --- B tile: Bs[k][d] = pW[d][kt+k], d = lrow
        {
            float v[8];
            if (kt + 16 <= K) {
                const float* base = pW + (size_t)lrow * K + kt + lc0;
                *(float4*)&v[0] = *(const float4*)(base);
                *(float4*)&v[4] = *(const float4*)(base + 4);
            } else {
#pragma unroll
                for (int j = 0; j < 8; j++) {
                    int kk = kt + lc0 + j;
                    v[j] = (kk < K) ? pW[(size_t)lrow * K + kk] : 0.0f;
                }
            }
#pragma unroll
            for (int j = 0; j < 8; j++) Bs[lc0 + j][lrow] = v[j];
        }
        __syncthreads();
#pragma unroll
        for (int k = 0; k < 16; k++) {
            float a[8], b[8];
            *(float4*)&a[0] = *(const float4*)&As[k][ty * 8];
            *(float4*)&a[4] = *(const float4*)&As[k][ty * 8 + 4];
            *(float4*)&b[0] = *(const float4*)&Bs[k][tx * 8];
            *(float4*)&b[4] = *(const float4*)&Bs[k][tx * 8 + 4];
#pragma unroll
            for (int i = 0; i < 8; i++)
#pragma unroll
                for (int j = 0; j < 8; j++) acc[i][j] += a[i] * b[j];
        }
        __syncthreads();
    }

    // epilogue: bias + lrelu + emb add
    float bj[8];
    *(float4*)&bj[0] = *(const float4*)(pb + tx * 8);
    *(float4*)&bj[4] = *(const float4*)(pb + tx * 8 + 4);
#pragma unroll
    for (int i = 0; i < 8; i++) {
        int n = nb + ty * 8 + i;
        if (n >= N_NODES) continue;
        float e[8];
        *(float4*)&e[0] = *(const float4*)(emb + (size_t)(n + 1) * D + tx * 8);
        *(float4*)&e[4] = *(const float4*)(emb + (size_t)(n + 1) * D + tx * 8 + 4);
        float o[8];
#pragma unroll
        for (int j = 0; j < 8; j++) {
            float v = acc[i][j] + bj[j];
            v = (v > 0.0f) ? v : 0.1f * v;
            o[j] = v + e[j];
        }
        *(float4*)(out + (size_t)n * D + tx * 8)     = *(float4*)&o[0];
        *(float4*)(out + (size_t)n * D + tx * 8 + 4) = *(float4*)&o[4];
    }
}

// SAGE layer: X = [h, hagg] (hagg pre-scaled); out = normalize(act(X @ W^T + b))
__global__ __launch_bounds__(256) void k_sage(const float* __restrict__ h,
                                              const float* __restrict__ W,
                                              const float* __restrict__ bias,
                                              float* __restrict__ out,
                                              int use_act) {
    __shared__ float As[16][132];
    __shared__ float Bs[16][132];
    int tid = threadIdx.x;
    int tx = tid & 15, ty = tid >> 4;
    int nb = blockIdx.x * 128;
    int lrow = tid >> 1;
    int lc0  = (tid & 1) * 8;

    float acc[8][8];
#pragma unroll
    for (int i = 0; i < 8; i++)
#pragma unroll
        for (int j = 0; j < 8; j++) acc[i][j] = 0.0f;

    for (int kt = 0; kt < 256; kt += 16) {
        // --- A tile
        {
            int n = nb + lrow;
            float v[8];
            bool agg = (kt >= 128);
            if (n < N_NODES) {
                const float* base = agg
                    ? (g_hagg + (size_t)n * D + (kt - 128) + lc0)
                    : (h + (size_t)n * D + kt + lc0);
                *(float4*)&v[0] = *(const float4*)(base);
                *(float4*)&v[4] = *(const float4*)(base + 4);
            } else {
#pragma unroll
                for (int j = 0; j < 8; j++) v[j] = 0.0f;
            }
#pragma unroll
            for (int j = 0; j < 8; j++) As[lc0 + j][lrow] = v[j];
        }
        // --- B tile: Bs[k][d] = W[d][kt+k], d = lrow
        {
            const float* base = W + (size_t)lrow * 256 + kt + lc0;
            float v[8];
            *(float4*)&v[0] = *(const float4*)(base);
            *(float4*)&v[4] = *(const float4*)(base + 4);
#pragma unroll
            for (int j = 0; j < 8; j++) Bs[lc0 + j][lrow] = v[j];
        }
        __syncthreads();
#pragma unroll
        for (int k = 0; k < 16; k++) {
            float a[8], b[8];
            *(float4*)&a[0] = *(const float4*)&As[k][ty * 8];
            *(float4*)&a[4] = *(const float4*)&As[k][ty * 8 + 4];
            *(float4*)&b[0] = *(const float4*)&Bs[k][tx * 8];
            *(float4*)&b[4] = *(const float4*)&Bs[k][tx * 8 + 4];
#pragma unroll
            for (int i = 0; i < 8; i++)
#pragma unroll
                for (int j = 0; j < 8; j++) acc[i][j] += a[i] * b[j];
        }
        __syncthreads();
    }

    // epilogue: bias + optional lrelu + row L2 norm (16 threads own a row)
    float bj[8];
    *(float4*)&bj[0] = *(const float4*)(bias + tx * 8);
    *(float4*)&bj[4] = *(const float4*)(bias + tx * 8 + 4);
    float inv[8];
#pragma unroll
    for (int i = 0; i < 8; i++) {
        float s = 0.0f;
#pragma unroll
        for (int j = 0; j < 8; j++) {
            float v = acc[i][j] + bj[j];
            if (use_act) v = (v > 0.0f) ? v : 0.1f * v;
            acc[i][j] = v;
            s += v * v;
        }
        s += __shfl_xor_sync(0xFFFFFFFFu, s, 1);
        s += __shfl_xor_sync(0xFFFFFFFFu, s, 2);
        s += __shfl_xor_sync(0xFFFFFFFFu, s, 4);
        s += __shfl_xor_sync(0xFFFFFFFFu, s, 8);
        inv[i] = 1.0f / fmaxf(sqrtf(s), 1e-6f);
    }
#pragma unroll
    for (int i = 0; i < 8; i++) {
        int n = nb + ty * 8 + i;
        if (n >= N_NODES) continue;
        float o[8];
#pragma unroll
        for (int j = 0; j < 8; j++) o[j] = acc[i][j] * inv[i];
        *(float4*)(out + (size_t)n * D + tx * 8)     = *(float4*)&o[0];
        *(float4*)(out + (size_t)n * D + tx * 8 + 4) = *(float4*)&o[4];
    }
}

// ---------------------------------------------------------------------------
extern "C" void kernel_launch(void* const* d_in, const int* in_sizes, int n_in,
                              void* d_out, int out_size) {
    const float* node_emb = (const float*)d_in[0];
    const float* content  = (const float*)d_in[1];
    const float* proj_W   = (const float*)d_in[2];
    const float* proj_b   = (const float*)d_in[3];
    const float* W1       = (const float*)d_in[4];
    const float* b1       = (const float*)d_in[5];
    const float* W2       = (const float*)d_in[6];
    const float* b2       = (const float*)d_in[7];
    const int*   esrc     = (const int*)d_in[8];
    const int*   edst     = (const int*)d_in[9];
    int etot = in_sizes[8];
    float* out = (float*)d_out;

    float *h0, *h1;
    cudaGetSymbolAddress((void**)&h0, g_h0);
    cudaGetSymbolAddress((void**)&h1, g_h1);

    int n_blocks  = (N_NODES + 255) / 256;
    int e_blocks  = (etot + 255) / 256;
    int gw_blocks = (N_NODES * 32 + 255) / 256;   // 1 warp per node
    int gemm_blocks = (N_NODES + 127) / 128;      // 391

    // CSR build (same graph both layers)
    k_zero_cnt<<<n_blocks, 256>>>();
    k_hist<<<e_blocks, 256>>>(edst, etot);
    k_scan<<<1, SCAN_T>>>(etot);
    k_fill<<<e_blocks, 256>>>(esrc, edst, etot);

    // h0 = emb + lrelu(content @ projW^T + b)
    k_mix<<<gemm_blocks, 256>>>(content, proj_W, proj_b, node_emb, h0);

    // layer 1
    k_gather<<<gw_blocks, 256>>>(h0);
    k_sage<<<gemm_blocks, 256>>>(h0, W1, b1, h1, 1);

    // layer 2
    k_gather<<<gw_blocks, 256>>>(h1);
    k_sage<<<gemm_blocks, 256>>>(h1, W2, b2, out, 0);
}

// round 5
// speedup vs baseline: 2.9766x; 1.3304x over previous
#include <cuda_runtime.h>
#include <cuda_bf16.h>
#include <math.h>
#include <stdint.h>

#define N_NODES 50000
#define D 128
#define E_MAX 1700000

// scratch (device globals -- no allocation allowed)
__device__ float g_h0[N_NODES * D];
__device__ float g_h1[N_NODES * D];
__device__ float g_invdeg[N_NODES];
__device__ int   g_cnt[N_NODES];
__device__ int   g_off[N_NODES + 1];
__device__ int   g_csrc[E_MAX];
// bf16 hi|lo panels
__device__ __nv_bfloat16 g_cbf[N_NODES * 640];   // content: Kp=320, [hi(320)|lo(320)]
__device__ __nv_bfloat16 g_xbf[N_NODES * 512];   // sage X:  Kp=256, [h_hi,hagg_hi|h_lo,hagg_lo]
__device__ __nv_bfloat16 g_wmix[128 * 640];
__device__ __nv_bfloat16 g_w1[128 * 512];
__device__ __nv_bfloat16 g_w2[128 * 512];

// ---------------------------------------------------------------------------
// CSR build: histogram -> scan -> fill
// ---------------------------------------------------------------------------
__global__ void k_zero_cnt() {
    int i = blockIdx.x * blockDim.x + threadIdx.x;
    if (i < N_NODES) g_cnt[i] = 0;
}

__global__ void k_hist(const int* __restrict__ dst, int etot) {
    int i = blockIdx.x * blockDim.x + threadIdx.x;
    if (i < etot) atomicAdd(&g_cnt[dst[i]], 1);
}

#define SCAN_T 1024
__global__ __launch_bounds__(SCAN_T) void k_scan(int etot) {
    __shared__ int sm[SCAN_T];
    int t = threadIdx.x;
    const int per = (N_NODES + SCAN_T - 1) / SCAN_T;
    int b = t * per;
    int e = min(b + per, N_NODES);
    int s = 0;
    for (int i = b; i < e; i++) s += g_cnt[i];
    sm[t] = s;
    __syncthreads();
    for (int d = 1; d < SCAN_T; d <<= 1) {
        int v = (t >= d) ? sm[t - d] : 0;
        __syncthreads();
        sm[t] += v;
        __syncthreads();
    }
    int run = (t == 0) ? 0 : sm[t - 1];
    for (int i = b; i < e; i++) {
        int c = g_cnt[i];
        g_off[i] = run;
        g_cnt[i] = run;  // becomes fill cursor
        g_invdeg[i] = 1.0f / fmaxf((float)c - 1.0f, 1.0f);
        run += c;
    }
    if (t == SCAN_T - 1) g_off[N_NODES] = etot;
}

__global__ void k_fill(const int* __restrict__ src, const int* __restrict__ dst,
                       int etot) {
    int i = blockIdx.x * blockDim.x + threadIdx.x;
    if (i < etot) {
        int slot = atomicAdd(&g_cnt[dst[i]], 1);
        g_csrc[slot] = src[i];
    }
}

// ---------------------------------------------------------------------------
// bf16 hi/lo helpers
// ---------------------------------------------------------------------------
__device__ __forceinline__ void split_bf16(float x, unsigned short& hi,
                                           unsigned short& lo) {
    __nv_bfloat16 h = __float2bfloat16(x);
    __nv_bfloat16 l = __float2bfloat16(x - __bfloat162float(h));
    hi = __bfloat16_as_ushort(h);
    lo = __bfloat16_as_ushort(l);
}

// ---------------------------------------------------------------------------
// prep: content [N][300] -> g_cbf [N][640]  (pad to 320, hi | lo)
// ---------------------------------------------------------------------------
__global__ void k_prep_content(const float* __restrict__ content) {
    int gid = blockIdx.x * blockDim.x + threadIdx.x;
    if (gid >= N_NODES * 40) return;
    int n = gid / 40, c0 = (gid % 40) * 8;
    unsigned short h[8], l[8];
#pragma unroll
    for (int j = 0; j < 8; j++) {
        int c = c0 + j;
        float v = (c < 300) ? content[(size_t)n * 300 + c] : 0.0f;
        split_bf16(v, h[j], l[j]);
    }
    *(uint4*)(g_cbf + (size_t)n * 640 + c0)       = *(uint4*)h;
    *(uint4*)(g_cbf + (size_t)n * 640 + 320 + c0) = *(uint4*)l;
}

// prep: W [128][Ksrc] -> dst [128][2*Kp]
__global__ void k_prep_w(const float* __restrict__ W, int Ksrc, int Kp,
                         __nv_bfloat16* __restrict__ dst) {
    int gid = blockIdx.x * blockDim.x + threadIdx.x;
    int groups = Kp / 8;
    if (gid >= 128 * groups) return;
    int d = gid / groups, c0 = (gid % groups) * 8;
    unsigned short h[8], l[8];
#pragma unroll
    for (int j = 0; j < 8; j++) {
        int c = c0 + j;
        float v = (c < Ksrc) ? W[(size_t)d * Ksrc + c] : 0.0f;
        split_bf16(v, h[j], l[j]);
    }
    *(uint4*)(dst + (size_t)d * 2 * Kp + c0)      = *(uint4*)h;
    *(uint4*)(dst + (size_t)d * 2 * Kp + Kp + c0) = *(uint4*)l;
}

// ---------------------------------------------------------------------------
// gather: one warp per node.  agg = (sum_in - self) * invdeg.
// Writes g_xbf[n] = [hi(self)(0:128) hi(agg)(128:256) | lo(self) lo(agg)]
// ---------------------------------------------------------------------------
__global__ __launch_bounds__(256) void k_gather(const float* __restrict__ h) {
    int warp = (blockIdx.x * blockDim.x + threadIdx.x) >> 5;
    int lane = threadIdx.x & 31;
    if (warp >= N_NODES) return;
    int beg = g_off[warp], end = g_off[warp + 1];

    float4 self = ((const float4*)(h + (size_t)warp * D))[lane];
    float ax = -self.x, ay = -self.y, az = -self.z, aw = -self.w;

    int e = beg;
    for (; e + 4 <= end; e += 4) {
        int s0 = __ldg(&g_csrc[e + 0]);
        int s1 = __ldg(&g_csrc[e + 1]);
        int s2 = __ldg(&g_csrc[e + 2]);
        int s3 = __ldg(&g_csrc[e + 3]);
        float4 v0 = ((const float4*)(h + (size_t)s0 * D))[lane];
        float4 v1 = ((const float4*)(h + (size_t)s1 * D))[lane];
        float4 v2 = ((const float4*)(h + (size_t)s2 * D))[lane];
        float4 v3 = ((const float4*)(h + (size_t)s3 * D))[lane];
        ax += (v0.x + v1.x) + (v2.x + v3.x);
        ay += (v0.y + v1.y) + (v2.y + v3.y);
        az += (v0.z + v1.z) + (v2.z + v3.z);
        aw += (v0.w + v1.w) + (v2.w + v3.w);
    }
    for (; e < end; e++) {
        int s0 = __ldg(&g_csrc[e]);
        float4 v0 = ((const float4*)(h + (size_t)s0 * D))[lane];
        ax += v0.x; ay += v0.y; az += v0.z; aw += v0.w;
    }
    float sc = g_invdeg[warp];
    float agg[4] = {ax * sc, ay * sc, az * sc, aw * sc};
    float slf[4] = {self.x, self.y, self.z, self.w};

    unsigned short sh[4], sl[4], gh[4], gl[4];
#pragma unroll
    for (int j = 0; j < 4; j++) {
        split_bf16(slf[j], sh[j], sl[j]);
        split_bf16(agg[j], gh[j], gl[j]);
    }
    __nv_bfloat16* row = g_xbf + (size_t)warp * 512;
    *(uint2*)(row + lane * 4)       = *(uint2*)sh;
    *(uint2*)(row + 128 + lane * 4) = *(uint2*)gh;
    *(uint2*)(row + 256 + lane * 4) = *(uint2*)sl;
    *(uint2*)(row + 384 + lane * 4) = *(uint2*)gl;
}

// ---------------------------------------------------------------------------
// bf16 mma GEMM: out[128 rows x 128 cols per CTA] = A(2Kp hi|lo) @ W^T
// 3-product split: Ahi*Bhi + Ahi*Blo + Alo*Bhi, fp32 accumulate.
// 8 warps: warp (wm=wid&3, wn=wid>>2) computes 32x64.
// mode: 0 = mix (bias+lrelu+emb add), 1 = sage lrelu+norm, 2 = sage norm
// ---------------------------------------------------------------------------
#define LDMX4(R, ADDR)                                                         \
    asm volatile("ldmatrix.sync.aligned.m8n8.x4.shared.b16 {%0,%1,%2,%3}, [%4];" \
                 : "=r"((R)[0]), "=r"((R)[1]), "=r"((R)[2]), "=r"((R)[3])      \
                 : "r"(ADDR))

#define MMA16816(DD, AA, B0, B1)                                               \
    asm volatile(                                                              \
        "mma.sync.aligned.m16n8k16.row.col.f32.bf16.bf16.f32 "                 \
        "{%0,%1,%2,%3}, {%4,%5,%6,%7}, {%8,%9}, {%0,%1,%2,%3};"                \
        : "+f"((DD)[0]), "+f"((DD)[1]), "+f"((DD)[2]), "+f"((DD)[3])           \
        : "r"((AA)[0]), "r"((AA)[1]), "r"((AA)[2]), "r"((AA)[3]),              \
          "r"(B0), "r"(B1))

__global__ __launch_bounds__(256) void k_gemm(const __nv_bfloat16* __restrict__ A,
                                              int Kp,
                                              const __nv_bfloat16* __restrict__ Wb,
                                              const float* __restrict__ bias,
                                              const float* __restrict__ emb,
                                              float* __restrict__ out, int mode) {
    __shared__ __align__(16) __nv_bfloat16 sA[2][128 * 40];  // 80B row stride
    __shared__ __align__(16) __nv_bfloat16 sB[2][128 * 40];
    __shared__ float s_bias[128];
    __shared__ float s_rs[128][2];

    int tid = threadIdx.x, lane = tid & 31, wid = tid >> 5;
    int wm = wid & 3, wn = wid >> 2;
    int nb = blockIdx.x * 128;

    if (tid < 128) s_bias[tid] = bias[tid];

    float acc[2][8][4];
#pragma unroll
    for (int mt = 0; mt < 2; mt++)
#pragma unroll
        for (int nt = 0; nt < 8; nt++)
#pragma unroll
            for (int r = 0; r < 4; r++) acc[mt][nt][r] = 0.0f;

    // ldmatrix byte offsets within an 80B-stride [128][40bf16] tile
    uint32_t aoff[2], boff[4];
#pragma unroll
    for (int mt = 0; mt < 2; mt++)
        aoff[mt] = (uint32_t)(wm * 32 + mt * 16 + (lane & 15)) * 80u +
                   ((lane >> 4) & 1) * 16u;
#pragma unroll
    for (int p = 0; p < 4; p++)
        boff[p] = (uint32_t)(wn * 64 + p * 16 + ((lane >> 4) & 1) * 8 + (lane & 7)) * 80u +
                  ((lane >> 3) & 1) * 16u;

    uint32_t sAh = (uint32_t)__cvta_generic_to_shared(sA[0]);
    uint32_t sAl = (uint32_t)__cvta_generic_to_shared(sA[1]);
    uint32_t sBh = (uint32_t)__cvta_generic_to_shared(sB[0]);
    uint32_t sBl = (uint32_t)__cvta_generic_to_shared(sB[1]);

    // staging: thread -> row = tid/2, chunks {0,1} or {2,3} (16B each)
    int srow = tid >> 1;
    int sc0  = (tid & 1) * 2;
    bool avalid = (nb + srow) < N_NODES;
    const __nv_bfloat16* arow = A + (size_t)(nb + srow) * (2 * Kp);
    const __nv_bfloat16* brow = Wb + (size_t)srow * (2 * Kp);

#pragma unroll 1
    for (int kt = 0; kt < Kp; kt += 32) {
        uint4 z = make_uint4(0, 0, 0, 0);
#pragma unroll
        for (int i = 0; i < 2; i++) {
            int c = sc0 + i;
            int col = kt + c * 8;
            uint4 vah = avalid ? *(const uint4*)(arow + col) : z;
            uint4 val = avalid ? *(const uint4*)(arow + Kp + col) : z;
            uint4 vbh = *(const uint4*)(brow + col);
            uint4 vbl = *(const uint4*)(brow + Kp + col);
            int so = srow * 40 + c * 8;
            *(uint4*)(sA[0] + so) = vah;
            *(uint4*)(sA[1] + so) = val;
            *(uint4*)(sB[0] + so) = vbh;
            *(uint4*)(sB[1] + so) = vbl;
        }
        __syncthreads();
#pragma unroll
        for (int ks = 0; ks < 2; ks++) {
            uint32_t kb = ks * 32u;
            uint32_t ah[2][4], al[2][4];
            LDMX4(ah[0], sAh + aoff[0] + kb);
            LDMX4(ah[1], sAh + aoff[1] + kb);
            LDMX4(al[0], sAl + aoff[0] + kb);
            LDMX4(al[1], sAl + aoff[1] + kb);
#pragma unroll
            for (int p = 0; p < 4; p++) {
                uint32_t bh[4], bl[4];
                LDMX4(bh, sBh + boff[p] + kb);
#pragma unroll
                for (int t = 0; t < 2; t++) {
                    int nt = 2 * p + t;
                    MMA16816(acc[0][nt], ah[0], bh[2 * t], bh[2 * t + 1]);
                    MMA16816(acc[1][nt], ah[1], bh[2 * t], bh[2 * t + 1]);
                    MMA16816(acc[0][nt], al[0], bh[2 * t], bh[2 * t + 1]);
                    MMA16816(acc[1][nt], al[1], bh[2 * t], bh[2 * t + 1]);
                }
                LDMX4(bl, sBl + boff[p] + kb);
#pragma unroll
                for (int t = 0; t < 2; t++) {
                    int nt = 2 * p + t;
                    MMA16816(acc[0][nt], ah[0], bl[2 * t], bl[2 * t + 1]);
                    MMA16816(acc[1][nt], ah[1], bl[2 * t], bl[2 * t + 1]);
                }
            }
        }
        __syncthreads();
    }

    // ---------------- epilogue ----------------
    int q = lane >> 2;        // 0..7
    int rchunk = lane & 3;    // column pair selector

    if (mode == 0) {
        // mix: out = emb[n+1] + lrelu(D + bias)
#pragma unroll
        for (int mt = 0; mt < 2; mt++) {
            int lr0 = wm * 32 + mt * 16 + q;
            int r0 = nb + lr0, r1 = r0 + 8;
#pragma unroll
            for (int nt = 0; nt < 8; nt++) {
                int cb = wn * 64 + nt * 8 + 2 * rchunk;
                float b0 = s_bias[cb], b1 = s_bias[cb + 1];
                if (r0 < N_NODES) {
                    float2 e = *(const float2*)(emb + (size_t)(r0 + 1) * D + cb);
                    float v0 = acc[mt][nt][0] + b0;
                    float v1 = acc[mt][nt][1] + b1;
                    v0 = (v0 > 0.f) ? v0 : 0.1f * v0;
                    v1 = (v1 > 0.f) ? v1 : 0.1f * v1;
                    float2 o = make_float2(v0 + e.x, v1 + e.y);
                    *(float2*)(out + (size_t)r0 * D + cb) = o;
                }
                if (r1 < N_NODES) {
                    float2 e = *(const float2*)(emb + (size_t)(r1 + 1) * D + cb);
                    float v2 = acc[mt][nt][2] + b0;
                    float v3 = acc[mt][nt][3] + b1;
                    v2 = (v2 > 0.f) ? v2 : 0.1f * v2;
                    v3 = (v3 > 0.f) ? v3 : 0.1f * v3;
                    float2 o = make_float2(v2 + e.x, v3 + e.y);
                    *(float2*)(out + (size_t)r1 * D + cb) = o;
                }
            }
        }
    } else {
        // sage: bias + optional lrelu, then row L2 normalize
        float ssa[2] = {0.f, 0.f}, ssb[2] = {0.f, 0.f};
#pragma unroll
        for (int mt = 0; mt < 2; mt++) {
#pragma unroll
            for (int nt = 0; nt < 8; nt++) {
                int cb = wn * 64 + nt * 8 + 2 * rchunk;
                float b0 = s_bias[cb], b1 = s_bias[cb + 1];
                float v0 = acc[mt][nt][0] + b0;
                float v1 = acc[mt][nt][1] + b1;
                float v2 = acc[mt][nt][2] + b0;
                float v3 = acc[mt][nt][3] + b1;
                if (mode == 1) {
                    v0 = (v0 > 0.f) ? v0 : 0.1f * v0;
                    v1 = (v1 > 0.f) ? v1 : 0.1f * v1;
                    v2 = (v2 > 0.f) ? v2 : 0.1f * v2;
                    v3 = (v3 > 0.f) ? v3 : 0.1f * v3;
                }
                acc[mt][nt][0] = v0; acc[mt][nt][1] = v1;
                acc[mt][nt][2] = v2; acc[mt][nt][3] = v3;
                ssa[mt] += v0 * v0 + v1 * v1;
                ssb[mt] += v2 * v2 + v3 * v3;
            }
            ssa[mt] += __shfl_xor_sync(0xFFFFFFFFu, ssa[mt], 1);
            ssa[mt] += __shfl_xor_sync(0xFFFFFFFFu, ssa[mt], 2);
            ssb[mt] += __shfl_xor_sync(0xFFFFFFFFu, ssb[mt], 1);
            ssb[mt] += __shfl_xor_sync(0xFFFFFFFFu, ssb[mt], 2);
            if (rchunk == 0) {
                s_rs[wm * 32 + mt * 16 + q][wn]     = ssa[mt];
                s_rs[wm * 32 + mt * 16 + 8 + q][wn] = ssb[mt];
            }
        }
        __syncthreads();
#pragma unroll
        for (int mt = 0; mt < 2; mt++) {
            int lr0 = wm * 32 + mt * 16 + q;
            int r0 = nb + lr0, r1 = r0 + 8;
            float t0 = s_rs[lr0][0] + s_rs[lr0][1];
            float t1 = s_rs[lr0 + 8][0] + s_rs[lr0 + 8][1];
            float inv0 = 1.0f / fmaxf(sqrtf(t0), 1e-6f);
            float inv1 = 1.0f / fmaxf(sqrtf(t1), 1e-6f);
#pragma unroll
            for (int nt = 0; nt < 8; nt++) {
                int cb = wn * 64 + nt * 8 + 2 * rchunk;
                if (r0 < N_NODES) {
                    float2 o = make_float2(acc[mt][nt][0] * inv0,
                                           acc[mt][nt][1] * inv0);
                    *(float2*)(out + (size_t)r0 * D + cb) = o;
                }
                if (r1 < N_NODES) {
                    float2 o = make_float2(acc[mt][nt][2] * inv1,
                                           acc[mt][nt][3] * inv1);
                    *(float2*)(out + (size_t)r1 * D + cb) = o;
                }
            }
        }
    }
}

// ---------------------------------------------------------------------------
extern "C" void kernel_launch(void* const* d_in, const int* in_sizes, int n_in,
                              void* d_out, int out_size) {
    const float* node_emb = (const float*)d_in[0];
    const float* content  = (const float*)d_in[1];
    const float* proj_W   = (const float*)d_in[2];
    const float* proj_b   = (const float*)d_in[3];
    const float* W1       = (const float*)d_in[4];
    const float* b1       = (const float*)d_in[5];
    const float* W2       = (const float*)d_in[6];
    const float* b2       = (const float*)d_in[7];
    const int*   esrc     = (const int*)d_in[8];
    const int*   edst     = (const int*)d_in[9];
    int etot = in_sizes[8];
    float* out = (float*)d_out;

    float *h0, *h1;
    cudaGetSymbolAddress((void**)&h0, g_h0);
    cudaGetSymbolAddress((void**)&h1, g_h1);
    __nv_bfloat16 *cbf, *xbf, *wmix, *w1, *w2;
    cudaGetSymbolAddress((void**)&cbf, g_cbf);
    cudaGetSymbolAddress((void**)&xbf, g_xbf);
    cudaGetSymbolAddress((void**)&wmix, g_wmix);
    cudaGetSymbolAddress((void**)&w1, g_w1);
    cudaGetSymbolAddress((void**)&w2, g_w2);

    int n_blocks  = (N_NODES + 255) / 256;
    int e_blocks  = (etot + 255) / 256;
    int gw_blocks = (N_NODES * 32 + 255) / 256;   // 1 warp per node
    int gemm_blocks = (N_NODES + 127) / 128;      // 391

    // CSR build (same graph both layers)
    k_zero_cnt<<<n_blocks, 256>>>();
    k_hist<<<e_blocks, 256>>>(edst, etot);
    k_scan<<<1, SCAN_T>>>(etot);
    k_fill<<<e_blocks, 256>>>(esrc, edst, etot);

    // weight + content prep (bf16 hi|lo)
    k_prep_w<<<(128 * 40 + 255) / 256, 256>>>(proj_W, 300, 320, wmix);
    k_prep_w<<<(128 * 32 + 255) / 256, 256>>>(W1, 256, 256, w1);
    k_prep_w<<<(128 * 32 + 255) / 256, 256>>>(W2, 256, 256, w2);
    k_prep_content<<<(N_NODES * 40 + 255) / 256, 256>>>(content);

    // h0 = emb + lrelu(content @ projW^T + b)
    k_gemm<<<gemm_blocks, 256>>>(cbf, 320, wmix, proj_b, node_emb, h0, 0);

    // layer 1
    k_gather<<<gw_blocks, 256>>>(h0);
    k_gemm<<<gemm_blocks, 256>>>(xbf, 256, w1, b1, nullptr, h1, 1);

    // layer 2
    k_gather<<<gw_blocks, 256>>>(h1);
    k_gemm<<<gemm_blocks, 256>>>(xbf, 256, w2, b2, nullptr, out, 2);
}

// round 6
// speedup vs baseline: 3.5020x; 1.1765x over previous
#include <cuda_runtime.h>
#include <cuda_bf16.h>
#include <math.h>
#include <stdint.h>

#define N_NODES 50000
#define D 128
#define E_MAX 1700000

// scratch (device globals -- no allocation allowed)
__device__ float g_h0[N_NODES * D];
__device__ float g_h1[N_NODES * D];
__device__ float g_invdeg[N_NODES];
__device__ int   g_cnt[N_NODES];
__device__ int   g_off[N_NODES + 1];
__device__ int   g_csrc[E_MAX];
// bf16 hi|lo panels
__device__ __nv_bfloat16 g_xbf[N_NODES * 512];   // sage X: [h_hi,agg_hi | h_lo,agg_lo]
__device__ __nv_bfloat16 g_wmix[128 * 640];      // Kp=320 hi|lo
__device__ __nv_bfloat16 g_w1[128 * 512];        // Kp=256 hi|lo
__device__ __nv_bfloat16 g_w2[128 * 512];

// ---------------------------------------------------------------------------
// CSR build: histogram -> scan -> fill
// ---------------------------------------------------------------------------
__global__ void k_zero_cnt() {
    int i = blockIdx.x * blockDim.x + threadIdx.x;
    if (i < N_NODES) g_cnt[i] = 0;
}

__global__ void k_hist(const int* __restrict__ dst, int etot) {
    int i = blockIdx.x * blockDim.x + threadIdx.x;
    if (i < etot) atomicAdd(&g_cnt[dst[i]], 1);
}

#define SCAN_T 1024
__global__ __launch_bounds__(SCAN_T) void k_scan(int etot) {
    __shared__ int sm[SCAN_T];
    int t = threadIdx.x;
    const int per = (N_NODES + SCAN_T - 1) / SCAN_T;
    int b = t * per;
    int e = min(b + per, N_NODES);
    int s = 0;
    for (int i = b; i < e; i++) s += g_cnt[i];
    sm[t] = s;
    __syncthreads();
    for (int d = 1; d < SCAN_T; d <<= 1) {
        int v = (t >= d) ? sm[t - d] : 0;
        __syncthreads();
        sm[t] += v;
        __syncthreads();
    }
    int run = (t == 0) ? 0 : sm[t - 1];
    for (int i = b; i < e; i++) {
        int c = g_cnt[i];
        g_off[i] = run;
        g_cnt[i] = run;  // becomes fill cursor
        g_invdeg[i] = 1.0f / fmaxf((float)c - 1.0f, 1.0f);
        run += c;
    }
    if (t == SCAN_T - 1) g_off[N_NODES] = etot;
}

__global__ void k_fill(const int* __restrict__ src, const int* __restrict__ dst,
                       int etot) {
    int i = blockIdx.x * blockDim.x + threadIdx.x;
    if (i < etot) {
        int slot = atomicAdd(&g_cnt[dst[i]], 1);
        g_csrc[slot] = src[i];
    }
}

// ---------------------------------------------------------------------------
// bf16 hi/lo helpers
// ---------------------------------------------------------------------------
__device__ __forceinline__ void split_bf16(float x, unsigned short& hi,
                                           unsigned short& lo) {
    __nv_bfloat16 h = __float2bfloat16(x);
    __nv_bfloat16 l = __float2bfloat16(x - __bfloat162float(h));
    hi = __bfloat16_as_ushort(h);
    lo = __bfloat16_as_ushort(l);
}

// all three weights -> hi|lo bf16 panels, one launch
__global__ void k_prep_w_all(const float* __restrict__ pW,
                             const float* __restrict__ W1,
                             const float* __restrict__ W2) {
    int gid = blockIdx.x * blockDim.x + threadIdx.x;
    const float* W;
    __nv_bfloat16* dst;
    int Ksrc, Kp, g;
    if (gid < 128 * 40) {
        W = pW; dst = g_wmix; Ksrc = 300; Kp = 320; g = gid;
    } else if (gid < 128 * 40 + 128 * 32) {
        W = W1; dst = g_w1; Ksrc = 256; Kp = 256; g = gid - 128 * 40;
    } else if (gid < 128 * 40 + 2 * 128 * 32) {
        W = W2; dst = g_w2; Ksrc = 256; Kp = 256; g = gid - 128 * 40 - 128 * 32;
    } else {
        return;
    }
    int groups = Kp / 8;
    int d = g / groups, c0 = (g % groups) * 8;
    unsigned short h[8], l[8];
#pragma unroll
    for (int j = 0; j < 8; j++) {
        int c = c0 + j;
        float v = (c < Ksrc) ? W[(size_t)d * Ksrc + c] : 0.0f;
        split_bf16(v, h[j], l[j]);
    }
    *(uint4*)(dst + (size_t)d * 2 * Kp + c0)      = *(uint4*)h;
    *(uint4*)(dst + (size_t)d * 2 * Kp + Kp + c0) = *(uint4*)l;
}

// ---------------------------------------------------------------------------
// gather: one warp per node.  agg = (sum_in - self) * invdeg.
// Writes g_xbf[n] = [hi(self) hi(agg) | lo(self) lo(agg)]
// ---------------------------------------------------------------------------
__global__ __launch_bounds__(256) void k_gather(const float* __restrict__ h) {
    int warp = (blockIdx.x * blockDim.x + threadIdx.x) >> 5;
    int lane = threadIdx.x & 31;
    if (warp >= N_NODES) return;
    int beg = g_off[warp], end = g_off[warp + 1];

    float4 self = ((const float4*)(h + (size_t)warp * D))[lane];
    float ax = -self.x, ay = -self.y, az = -self.z, aw = -self.w;

    int e = beg;
    for (; e + 4 <= end; e += 4) {
        int s0 = __ldg(&g_csrc[e + 0]);
        int s1 = __ldg(&g_csrc[e + 1]);
        int s2 = __ldg(&g_csrc[e + 2]);
        int s3 = __ldg(&g_csrc[e + 3]);
        float4 v0 = ((const float4*)(h + (size_t)s0 * D))[lane];
        float4 v1 = ((const float4*)(h + (size_t)s1 * D))[lane];
        float4 v2 = ((const float4*)(h + (size_t)s2 * D))[lane];
        float4 v3 = ((const float4*)(h + (size_t)s3 * D))[lane];
        ax += (v0.x + v1.x) + (v2.x + v3.x);
        ay += (v0.y + v1.y) + (v2.y + v3.y);
        az += (v0.z + v1.z) + (v2.z + v3.z);
        aw += (v0.w + v1.w) + (v2.w + v3.w);
    }
    for (; e < end; e++) {
        int s0 = __ldg(&g_csrc[e]);
        float4 v0 = ((const float4*)(h + (size_t)s0 * D))[lane];
        ax += v0.x; ay += v0.y; az += v0.z; aw += v0.w;
    }
    float sc = g_invdeg[warp];
    float agg[4] = {ax * sc, ay * sc, az * sc, aw * sc};
    float slf[4] = {self.x, self.y, self.z, self.w};

    unsigned short sh[4], sl[4], gh[4], gl[4];
#pragma unroll
    for (int j = 0; j < 4; j++) {
        split_bf16(slf[j], sh[j], sl[j]);
        split_bf16(agg[j], gh[j], gl[j]);
    }
    __nv_bfloat16* row = g_xbf + (size_t)warp * 512;
    *(uint2*)(row + lane * 4)       = *(uint2*)sh;
    *(uint2*)(row + 128 + lane * 4) = *(uint2*)gh;
    *(uint2*)(row + 256 + lane * 4) = *(uint2*)sl;
    *(uint2*)(row + 384 + lane * 4) = *(uint2*)gl;
}

// ---------------------------------------------------------------------------
// pipelined bf16 mma GEMM, 128x128 CTA tile, 256 threads
// A: either prepped bf16 hi|lo (sage) or raw fp32 content (mix, converted
//    in-staging).  B: prepped bf16 hi|lo weights via cp.async double buffer.
// 3-product split: Ahi*Bhi + Ahi*Blo + Alo*Bhi, fp32 accumulate.
// mode: 0 = mix (bias+lrelu+emb add), 1 = sage lrelu+norm, 2 = sage norm
// ---------------------------------------------------------------------------
#define LDMX4(R, ADDR)                                                         \
    asm volatile("ldmatrix.sync.aligned.m8n8.x4.shared.b16 {%0,%1,%2,%3}, [%4];" \
                 : "=r"((R)[0]), "=r"((R)[1]), "=r"((R)[2]), "=r"((R)[3])      \
                 : "r"(ADDR))

#define MMA16816(DD, AA, B0, B1)                                               \
    asm volatile(                                                              \
        "mma.sync.aligned.m16n8k16.row.col.f32.bf16.bf16.f32 "                 \
        "{%0,%1,%2,%3}, {%4,%5,%6,%7}, {%8,%9}, {%0,%1,%2,%3};"                \
        : "+f"((DD)[0]), "+f"((DD)[1]), "+f"((DD)[2]), "+f"((DD)[3])           \
        : "r"((AA)[0]), "r"((AA)[1]), "r"((AA)[2]), "r"((AA)[3]),              \
          "r"(B0), "r"(B1))

#define CP16(DST, SRC)                                                         \
    asm volatile("cp.async.cg.shared.global [%0], [%1], 16;" :: "r"(DST),      \
                 "l"(SRC) : "memory")
#define CP_COMMIT() asm volatile("cp.async.commit_group;" ::: "memory")
#define CP_WAIT0()  asm volatile("cp.async.wait_group 0;" ::: "memory")

#define TILE_BF 5120          // 128 rows * 40 bf16 (80B stride)
#define TILE_BYTES 10240
#define GEMM_SMEM (8 * TILE_BYTES)   // A[2][2] + B[2][2] tiles

__global__ __launch_bounds__(256, 2) void k_gemm(
    const __nv_bfloat16* __restrict__ Abf,    // sage panel (or null)
    const float* __restrict__ Af32,           // mix content (or null)
    int Kp,
    const __nv_bfloat16* __restrict__ Wb,
    const float* __restrict__ bias,
    const float* __restrict__ emb,
    float* __restrict__ out, int mode) {
    extern __shared__ __nv_bfloat16 smem[];
    __nv_bfloat16* sA = smem;                 // [stage][hi/lo][TILE_BF]
    __nv_bfloat16* sB = smem + 4 * TILE_BF;
    __shared__ float s_bias[128];
    __shared__ float s_rs[128][2];

    int tid = threadIdx.x, lane = tid & 31, wid = tid >> 5;
    int wm = wid & 3, wn = wid >> 2;
    int nb = blockIdx.x * 128;

    if (tid < 128) s_bias[tid] = bias[tid];

    float acc[2][8][4];
#pragma unroll
    for (int mt = 0; mt < 2; mt++)
#pragma unroll
        for (int nt = 0; nt < 8; nt++)
#pragma unroll
            for (int r = 0; r < 4; r++) acc[mt][nt][r] = 0.0f;

    // ldmatrix byte offsets within one [128][40] bf16 tile
    uint32_t aoff[2], boff[4];
#pragma unroll
    for (int mt = 0; mt < 2; mt++)
        aoff[mt] = (uint32_t)(wm * 32 + mt * 16 + (lane & 15)) * 80u +
                   ((lane >> 4) & 1) * 16u;
#pragma unroll
    for (int p = 0; p < 4; p++)
        boff[p] = (uint32_t)(wn * 64 + p * 16 + ((lane >> 4) & 1) * 8 + (lane & 7)) * 80u +
                  ((lane >> 3) & 1) * 16u;

    uint32_t sAu = (uint32_t)__cvta_generic_to_shared(sA);
    uint32_t sBu = (uint32_t)__cvta_generic_to_shared(sB);

    // staging geometry: row = tid/2, 16 cols starting at (tid&1)*16
    int srow = tid >> 1;
    int c16  = (tid & 1) * 16;       // col offset within 32-col chunk
    bool avalid = (nb + srow) < N_NODES;
    const __nv_bfloat16* abrow = Abf ? (Abf + (size_t)(nb + srow) * (2 * Kp)) : nullptr;
    const float* afrow = Af32 ? (Af32 + (size_t)(nb + srow) * 300) : nullptr;
    const __nv_bfloat16* brow = Wb + (size_t)srow * (2 * Kp);
    uint32_t sdst = (uint32_t)(srow * 80 + c16 * 2);   // byte offset in tile

    uint4 Abuf[4];
    int nch = Kp / 32;

    // ---- lambdas (macros in spirit) ----
#define STAGE_B(KT, STG)                                                       \
    do {                                                                       \
        const __nv_bfloat16* _s = brow + (KT) + c16;                           \
        uint32_t _d = sBu + (uint32_t)(STG) * 2u * TILE_BYTES + sdst;          \
        CP16(_d, _s); CP16(_d + 16, _s + 8);                                   \
        const __nv_bfloat16* _sl = _s + Kp;                                    \
        uint32_t _dl = _d + TILE_BYTES;                                        \
        CP16(_dl, _sl); CP16(_dl + 16, _sl + 8);                               \
        CP_COMMIT();                                                           \
    } while (0)

#define LOAD_A(KT)                                                             \
    do {                                                                       \
        if (Abf) {                                                             \
            if (avalid) {                                                      \
                Abuf[0] = *(const uint4*)(abrow + (KT) + c16);                 \
                Abuf[1] = *(const uint4*)(abrow + (KT) + c16 + 8);             \
                Abuf[2] = *(const uint4*)(abrow + Kp + (KT) + c16);            \
                Abuf[3] = *(const uint4*)(abrow + Kp + (KT) + c16 + 8);        \
            } else {                                                           \
                Abuf[0] = Abuf[1] = Abuf[2] = Abuf[3] = make_uint4(0, 0, 0, 0);\
            }                                                                  \
        } else {                                                               \
            float v[16];                                                       \
            int col0 = (KT) + c16;                                             \
            if (avalid) {                                                      \
                _Pragma("unroll")                                              \
                for (int g = 0; g < 4; g++) {                                  \
                    int c = col0 + g * 4;                                      \
                    float4 f;                                                  \
                    if (c + 4 <= 300) f = *(const float4*)(afrow + c);         \
                    else f = make_float4(c + 0 < 300 ? afrow[c + 0] : 0.f,     \
                                         c + 1 < 300 ? afrow[c + 1] : 0.f,     \
                                         c + 2 < 300 ? afrow[c + 2] : 0.f,     \
                                         c + 3 < 300 ? afrow[c + 3] : 0.f);    \
                    v[g * 4 + 0] = f.x; v[g * 4 + 1] = f.y;                    \
                    v[g * 4 + 2] = f.z; v[g * 4 + 3] = f.w;                    \
                }                                                              \
            } else {                                                           \
                _Pragma("unroll")                                              \
                for (int j = 0; j < 16; j++) v[j] = 0.f;                       \
            }                                                                  \
            unsigned short hh[16], ll[16];                                     \
            _Pragma("unroll")                                                  \
            for (int j = 0; j < 16; j++) split_bf16(v[j], hh[j], ll[j]);       \
            Abuf[0] = *(uint4*)&hh[0]; Abuf[1] = *(uint4*)&hh[8];              \
            Abuf[2] = *(uint4*)&ll[0]; Abuf[3] = *(uint4*)&ll[8];              \
        }                                                                      \
    } while (0)

#define STORE_A(STG)                                                           \
    do {                                                                       \
        __nv_bfloat16* _h = sA + (size_t)(STG) * 2 * TILE_BF;                  \
        *(uint4*)((char*)_h + sdst)      = Abuf[0];                            \
        *(uint4*)((char*)_h + sdst + 16) = Abuf[1];                            \
        __nv_bfloat16* _l = _h + TILE_BF;                                      \
        *(uint4*)((char*)_l + sdst)      = Abuf[2];                            \
        *(uint4*)((char*)_l + sdst + 16) = Abuf[3];                            \
    } while (0)

    // prologue
    STAGE_B(0, 0);
    LOAD_A(0);
    STORE_A(0);
    CP_WAIT0();
    __syncthreads();

#pragma unroll 1
    for (int ch = 0; ch < nch; ch++) {
        int cur = ch & 1, nxt = cur ^ 1;
        if (ch + 1 < nch) {
            STAGE_B((ch + 1) * 32, nxt);
            LOAD_A((ch + 1) * 32);
        }
        // compute chunk ch from stage cur
        uint32_t bAh = sAu + (uint32_t)cur * 2u * TILE_BYTES;
        uint32_t bAl = bAh + TILE_BYTES;
        uint32_t bBh = sBu + (uint32_t)cur * 2u * TILE_BYTES;
        uint32_t bBl = bBh + TILE_BYTES;
#pragma unroll
        for (int ks = 0; ks < 2; ks++) {
            uint32_t kb = ks * 32u;
            uint32_t ah[2][4], al[2][4];
            LDMX4(ah[0], bAh + aoff[0] + kb);
            LDMX4(ah[1], bAh + aoff[1] + kb);
            LDMX4(al[0], bAl + aoff[0] + kb);
            LDMX4(al[1], bAl + aoff[1] + kb);
#pragma unroll
            for (int p = 0; p < 4; p++) {
                uint32_t bh[4], bl[4];
                LDMX4(bh, bBh + boff[p] + kb);
#pragma unroll
                for (int t = 0; t < 2; t++) {
                    int nt = 2 * p + t;
                    MMA16816(acc[0][nt], ah[0], bh[2 * t], bh[2 * t + 1]);
                    MMA16816(acc[1][nt], ah[1], bh[2 * t], bh[2 * t + 1]);
                    MMA16816(acc[0][nt], al[0], bh[2 * t], bh[2 * t + 1]);
                    MMA16816(acc[1][nt], al[1], bh[2 * t], bh[2 * t + 1]);
                }
                LDMX4(bl, bBl + boff[p] + kb);
#pragma unroll
                for (int t = 0; t < 2; t++) {
                    int nt = 2 * p + t;
                    MMA16816(acc[0][nt], ah[0], bl[2 * t], bl[2 * t + 1]);
                    MMA16816(acc[1][nt], ah[1], bl[2 * t], bl[2 * t + 1]);
                }
            }
        }
        if (ch + 1 < nch) STORE_A(nxt);
        CP_WAIT0();
        __syncthreads();
    }

    // ---------------- epilogue ----------------
    int q = lane >> 2;
    int rchunk = lane & 3;

    if (mode == 0) {
#pragma unroll
        for (int mt = 0; mt < 2; mt++) {
            int lr0 = wm * 32 + mt * 16 + q;
            int r0 = nb + lr0, r1 = r0 + 8;
#pragma unroll
            for (int nt = 0; nt < 8; nt++) {
                int cb = wn * 64 + nt * 8 + 2 * rchunk;
                float b0 = s_bias[cb], b1 = s_bias[cb + 1];
                if (r0 < N_NODES) {
                    float2 e = *(const float2*)(emb + (size_t)(r0 + 1) * D + cb);
                    float v0 = acc[mt][nt][0] + b0;
                    float v1 = acc[mt][nt][1] + b1;
                    v0 = (v0 > 0.f) ? v0 : 0.1f * v0;
                    v1 = (v1 > 0.f) ? v1 : 0.1f * v1;
                    float2 o = make_float2(v0 + e.x, v1 + e.y);
                    *(float2*)(out + (size_t)r0 * D + cb) = o;
                }
                if (r1 < N_NODES) {
                    float2 e = *(const float2*)(emb + (size_t)(r1 + 1) * D + cb);
                    float v2 = acc[mt][nt][2] + b0;
                    float v3 = acc[mt][nt][3] + b1;
                    v2 = (v2 > 0.f) ? v2 : 0.1f * v2;
                    v3 = (v3 > 0.f) ? v3 : 0.1f * v3;
                    float2 o = make_float2(v2 + e.x, v3 + e.y);
                    *(float2*)(out + (size_t)r1 * D + cb) = o;
                }
            }
        }
    } else {
        float ssa[2] = {0.f, 0.f}, ssb[2] = {0.f, 0.f};
#pragma unroll
        for (int mt = 0; mt < 2; mt++) {
#pragma unroll
            for (int nt = 0; nt < 8; nt++) {
                int cb = wn * 64 + nt * 8 + 2 * rchunk;
                float b0 = s_bias[cb], b1 = s_bias[cb + 1];
                float v0 = acc[mt][nt][0] + b0;
                float v1 = acc[mt][nt][1] + b1;
                float v2 = acc[mt][nt][2] + b0;
                float v3 = acc[mt][nt][3] + b1;
                if (mode == 1) {
                    v0 = (v0 > 0.f) ? v0 : 0.1f * v0;
                    v1 = (v1 > 0.f) ? v1 : 0.1f * v1;
                    v2 = (v2 > 0.f) ? v2 : 0.1f * v2;
                    v3 = (v3 > 0.f) ? v3 : 0.1f * v3;
                }
                acc[mt][nt][0] = v0; acc[mt][nt][1] = v1;
                acc[mt][nt][2] = v2; acc[mt][nt][3] = v3;
                ssa[mt] += v0 * v0 + v1 * v1;
                ssb[mt] += v2 * v2 + v3 * v3;
            }
            ssa[mt] += __shfl_xor_sync(0xFFFFFFFFu, ssa[mt], 1);
            ssa[mt] += __shfl_xor_sync(0xFFFFFFFFu, ssa[mt], 2);
            ssb[mt] += __shfl_xor_sync(0xFFFFFFFFu, ssb[mt], 1);
            ssb[mt] += __shfl_xor_sync(0xFFFFFFFFu, ssb[mt], 2);
            if (rchunk == 0) {
                s_rs[wm * 32 + mt * 16 + q][wn]     = ssa[mt];
                s_rs[wm * 32 + mt * 16 + 8 + q][wn] = ssb[mt];
            }
        }
        __syncthreads();
#pragma unroll
        for (int mt = 0; mt < 2; mt++) {
            int lr0 = wm * 32 + mt * 16 + q;
            int r0 = nb + lr0, r1 = r0 + 8;
            float t0 = s_rs[lr0][0] + s_rs[lr0][1];
            float t1 = s_rs[lr0 + 8][0] + s_rs[lr0 + 8][1];
            float inv0 = 1.0f / fmaxf(sqrtf(t0), 1e-6f);
            float inv1 = 1.0f / fmaxf(sqrtf(t1), 1e-6f);
#pragma unroll
            for (int nt = 0; nt < 8; nt++) {
                int cb = wn * 64 + nt * 8 + 2 * rchunk;
                if (r0 < N_NODES) {
                    float2 o = make_float2(acc[mt][nt][0] * inv0,
                                           acc[mt][nt][1] * inv0);
                    *(float2*)(out + (size_t)r0 * D + cb) = o;
                }
                if (r1 < N_NODES) {
                    float2 o = make_float2(acc[mt][nt][2] * inv1,
                                           acc[mt][nt][3] * inv1);
                    *(float2*)(out + (size_t)r1 * D + cb) = o;
                }
            }
        }
    }
}

// ---------------------------------------------------------------------------
extern "C" void kernel_launch(void* const* d_in, const int* in_sizes, int n_in,
                              void* d_out, int out_size) {
    const float* node_emb = (const float*)d_in[0];
    const float* content  = (const float*)d_in[1];
    const float* proj_W   = (const float*)d_in[2];
    const float* proj_b   = (const float*)d_in[3];
    const float* W1       = (const float*)d_in[4];
    const float* b1       = (const float*)d_in[5];
    const float* W2       = (const float*)d_in[6];
    const float* b2       = (const float*)d_in[7];
    const int*   esrc     = (const int*)d_in[8];
    const int*   edst     = (const int*)d_in[9];
    int etot = in_sizes[8];
    float* out = (float*)d_out;

    cudaFuncSetAttribute(k_gemm, cudaFuncAttributeMaxDynamicSharedMemorySize,
                         GEMM_SMEM);

    float *h0, *h1;
    cudaGetSymbolAddress((void**)&h0, g_h0);
    cudaGetSymbolAddress((void**)&h1, g_h1);
    __nv_bfloat16 *xbf, *wmix, *w1, *w2;
    cudaGetSymbolAddress((void**)&xbf, g_xbf);
    cudaGetSymbolAddress((void**)&wmix, g_wmix);
    cudaGetSymbolAddress((void**)&w1, g_w1);
    cudaGetSymbolAddress((void**)&w2, g_w2);

    int n_blocks  = (N_NODES + 255) / 256;
    int e_blocks  = (etot + 255) / 256;
    int gw_blocks = (N_NODES * 32 + 255) / 256;   // 1 warp per node
    int gemm_blocks = (N_NODES + 127) / 128;      // 391
    int prep_total = 128 * 40 + 2 * 128 * 32;

    // CSR build (same graph both layers)
    k_zero_cnt<<<n_blocks, 256>>>();
    k_hist<<<e_blocks, 256>>>(edst, etot);
    k_scan<<<1, SCAN_T>>>(etot);
    k_fill<<<e_blocks, 256>>>(esrc, edst, etot);

    // weight prep (bf16 hi|lo), single launch
    k_prep_w_all<<<(prep_total + 255) / 256, 256>>>(proj_W, W1, W2);

    // h0 = emb + lrelu(content @ projW^T + b)   (fp32 A converted in-kernel)
    k_gemm<<<gemm_blocks, 256, GEMM_SMEM>>>(nullptr, content, 320, wmix, proj_b,
                                            node_emb, h0, 0);

    // layer 1
    k_gather<<<gw_blocks, 256>>>(h0);
    k_gemm<<<gemm_blocks, 256, GEMM_SMEM>>>(xbf, nullptr, 256, w1, b1, nullptr,
                                            h1, 1);

    // layer 2
    k_gather<<<gw_blocks, 256>>>(h1);
    k_gemm<<<gemm_blocks, 256, GEMM_SMEM>>>(xbf, nullptr, 256, w2, b2, nullptr,
                                            out, 2);
}

// round 7
// speedup vs baseline: 4.1924x; 1.1972x over previous
#include <cuda_runtime.h>
#include <cuda_bf16.h>
#include <math.h>
#include <stdint.h>

#define N_NODES 50000
#define D 128
#define E_MAX 1700000

// scratch (device globals -- no allocation allowed)
__device__ float g_h0[N_NODES * D];
__device__ float g_h1[N_NODES * D];
__device__ float g_invdeg[N_NODES];
__device__ int   g_cnt[N_NODES];
__device__ int   g_off[N_NODES + 1];
__device__ int   g_csrc[E_MAX];
// bf16 hi|lo panels
__device__ __nv_bfloat16 g_xbf[N_NODES * 512];   // sage X: [h_hi,agg_hi | h_lo,agg_lo]
__device__ __nv_bfloat16 g_wmix[128 * 640];      // Kp=320 hi|lo
__device__ __nv_bfloat16 g_w1[128 * 512];        // Kp=256 hi|lo
__device__ __nv_bfloat16 g_w2[128 * 512];

// ---------------------------------------------------------------------------
// CSR build: histogram -> scan -> fill
// ---------------------------------------------------------------------------
__global__ void k_hist(const int* __restrict__ dst, int etot) {
    int i = blockIdx.x * blockDim.x + threadIdx.x;
    if (i < etot) atomicAdd(&g_cnt[dst[i]], 1);
}

#define SCAN_T 1024
__global__ __launch_bounds__(SCAN_T) void k_scan(int etot) {
    __shared__ int sm[SCAN_T];
    int t = threadIdx.x;
    const int per = (N_NODES + SCAN_T - 1) / SCAN_T;
    int b = t * per;
    int e = min(b + per, N_NODES);
    int s = 0;
    for (int i = b; i < e; i++) s += g_cnt[i];
    sm[t] = s;
    __syncthreads();
    for (int d = 1; d < SCAN_T; d <<= 1) {
        int v = (t >= d) ? sm[t - d] : 0;
        __syncthreads();
        sm[t] += v;
        __syncthreads();
    }
    int run = (t == 0) ? 0 : sm[t - 1];
    for (int i = b; i < e; i++) {
        int c = g_cnt[i];
        g_off[i] = run;
        g_cnt[i] = run;  // becomes fill cursor
        g_invdeg[i] = 1.0f / fmaxf((float)c - 1.0f, 1.0f);
        run += c;
    }
    if (t == SCAN_T - 1) g_off[N_NODES] = etot;
}

__global__ void k_fill(const int* __restrict__ src, const int* __restrict__ dst,
                       int etot) {
    int i = blockIdx.x * blockDim.x + threadIdx.x;
    if (i < etot) {
        int slot = atomicAdd(&g_cnt[dst[i]], 1);
        g_csrc[slot] = src[i];
    }
}

// ---------------------------------------------------------------------------
// bf16 hi/lo helpers
// ---------------------------------------------------------------------------
__device__ __forceinline__ void split_bf16(float x, unsigned short& hi,
                                           unsigned short& lo) {
    __nv_bfloat16 h = __float2bfloat16(x);
    __nv_bfloat16 l = __float2bfloat16(x - __bfloat162float(h));
    hi = __bfloat16_as_ushort(h);
    lo = __bfloat16_as_ushort(l);
}

// all three weights -> hi|lo bf16 panels, one launch
__global__ void k_prep_w_all(const float* __restrict__ pW,
                             const float* __restrict__ W1,
                             const float* __restrict__ W2) {
    int gid = blockIdx.x * blockDim.x + threadIdx.x;
    const float* W;
    __nv_bfloat16* dst;
    int Ksrc, Kp, g;
    if (gid < 128 * 40) {
        W = pW; dst = g_wmix; Ksrc = 300; Kp = 320; g = gid;
    } else if (gid < 128 * 40 + 128 * 32) {
        W = W1; dst = g_w1; Ksrc = 256; Kp = 256; g = gid - 128 * 40;
    } else if (gid < 128 * 40 + 2 * 128 * 32) {
        W = W2; dst = g_w2; Ksrc = 256; Kp = 256; g = gid - 128 * 40 - 128 * 32;
    } else {
        return;
    }
    int groups = Kp / 8;
    int d = g / groups, c0 = (g % groups) * 8;
    unsigned short h[8], l[8];
#pragma unroll
    for (int j = 0; j < 8; j++) {
        int c = c0 + j;
        float v = (c < Ksrc) ? W[(size_t)d * Ksrc + c] : 0.0f;
        split_bf16(v, h[j], l[j]);
    }
    *(uint4*)(dst + (size_t)d * 2 * Kp + c0)      = *(uint4*)h;
    *(uint4*)(dst + (size_t)d * 2 * Kp + Kp + c0) = *(uint4*)l;
}

// ---------------------------------------------------------------------------
// gather: one warp per node.  agg = (sum_in - self) * invdeg.
// Writes g_xbf[n] = [hi(self) hi(agg) | lo(self) lo(agg)]
// ---------------------------------------------------------------------------
__global__ __launch_bounds__(256) void k_gather(const float* __restrict__ h) {
    int warp = (blockIdx.x * blockDim.x + threadIdx.x) >> 5;
    int lane = threadIdx.x & 31;
    if (warp >= N_NODES) return;
    int beg = g_off[warp], end = g_off[warp + 1];

    float4 self = ((const float4*)(h + (size_t)warp * D))[lane];
    float ax = -self.x, ay = -self.y, az = -self.z, aw = -self.w;

    int e = beg;
    for (; e + 4 <= end; e += 4) {
        int s0 = __ldg(&g_csrc[e + 0]);
        int s1 = __ldg(&g_csrc[e + 1]);
        int s2 = __ldg(&g_csrc[e + 2]);
        int s3 = __ldg(&g_csrc[e + 3]);
        float4 v0 = ((const float4*)(h + (size_t)s0 * D))[lane];
        float4 v1 = ((const float4*)(h + (size_t)s1 * D))[lane];
        float4 v2 = ((const float4*)(h + (size_t)s2 * D))[lane];
        float4 v3 = ((const float4*)(h + (size_t)s3 * D))[lane];
        ax += (v0.x + v1.x) + (v2.x + v3.x);
        ay += (v0.y + v1.y) + (v2.y + v3.y);
        az += (v0.z + v1.z) + (v2.z + v3.z);
        aw += (v0.w + v1.w) + (v2.w + v3.w);
    }
    for (; e < end; e++) {
        int s0 = __ldg(&g_csrc[e]);
        float4 v0 = ((const float4*)(h + (size_t)s0 * D))[lane];
        ax += v0.x; ay += v0.y; az += v0.z; aw += v0.w;
    }
    float sc = g_invdeg[warp];
    float agg[4] = {ax * sc, ay * sc, az * sc, aw * sc};
    float slf[4] = {self.x, self.y, self.z, self.w};

    unsigned short sh[4], sl[4], gh[4], gl[4];
#pragma unroll
    for (int j = 0; j < 4; j++) {
        split_bf16(slf[j], sh[j], sl[j]);
        split_bf16(agg[j], gh[j], gl[j]);
    }
    __nv_bfloat16* row = g_xbf + (size_t)warp * 512;
    *(uint2*)(row + lane * 4)       = *(uint2*)sh;
    *(uint2*)(row + 128 + lane * 4) = *(uint2*)gh;
    *(uint2*)(row + 256 + lane * 4) = *(uint2*)sl;
    *(uint2*)(row + 384 + lane * 4) = *(uint2*)gl;
}

// ---------------------------------------------------------------------------
// pipelined bf16 mma GEMM, 128x128 CTA tile, 256 threads
// ---------------------------------------------------------------------------
#define LDMX4(R, ADDR)                                                         \
    asm volatile("ldmatrix.sync.aligned.m8n8.x4.shared.b16 {%0,%1,%2,%3}, [%4];" \
                 : "=r"((R)[0]), "=r"((R)[1]), "=r"((R)[2]), "=r"((R)[3])      \
                 : "r"(ADDR))

#define MMA16816(DD, AA, B0, B1)                                               \
    asm volatile(                                                              \
        "mma.sync.aligned.m16n8k16.row.col.f32.bf16.bf16.f32 "                 \
        "{%0,%1,%2,%3}, {%4,%5,%6,%7}, {%8,%9}, {%0,%1,%2,%3};"                \
        : "+f"((DD)[0]), "+f"((DD)[1]), "+f"((DD)[2]), "+f"((DD)[3])           \
        : "r"((AA)[0]), "r"((AA)[1]), "r"((AA)[2]), "r"((AA)[3]),              \
          "r"(B0), "r"(B1))

#define CP16(DST, SRC)                                                         \
    asm volatile("cp.async.cg.shared.global [%0], [%1], 16;" :: "r"(DST),      \
                 "l"(SRC) : "memory")
#define CP_COMMIT() asm volatile("cp.async.commit_group;" ::: "memory")
#define CP_WAIT0()  asm volatile("cp.async.wait_group 0;" ::: "memory")

#define TILE_BF 5120          // 128 rows * 40 bf16 (80B stride)
#define TILE_BYTES 10240
#define GEMM_SMEM (8 * TILE_BYTES)   // A[2][2] + B[2][2] tiles

__global__ __launch_bounds__(256, 2) void k_gemm(
    const __nv_bfloat16* __restrict__ Abf,    // sage panel (or null)
    const float* __restrict__ Af32,           // mix content (or null)
    int Kp,
    const __nv_bfloat16* __restrict__ Wb,
    const float* __restrict__ bias,
    const float* __restrict__ emb,
    float* __restrict__ out, int mode) {
    extern __shared__ __nv_bfloat16 smem[];
    __nv_bfloat16* sA = smem;                 // [stage][hi/lo][TILE_BF]
    __nv_bfloat16* sB = smem + 4 * TILE_BF;
    __shared__ float s_bias[128];
    __shared__ float s_rs[128][2];

    int tid = threadIdx.x, lane = tid & 31, wid = tid >> 5;
    int wm = wid & 3, wn = wid >> 2;
    int nb = blockIdx.x * 128;

    if (tid < 128) s_bias[tid] = bias[tid];

    float acc[2][8][4];
#pragma unroll
    for (int mt = 0; mt < 2; mt++)
#pragma unroll
        for (int nt = 0; nt < 8; nt++)
#pragma unroll
            for (int r = 0; r < 4; r++) acc[mt][nt][r] = 0.0f;

    uint32_t aoff[2], boff[4];
#pragma unroll
    for (int mt = 0; mt < 2; mt++)
        aoff[mt] = (uint32_t)(wm * 32 + mt * 16 + (lane & 15)) * 80u +
                   ((lane >> 4) & 1) * 16u;
#pragma unroll
    for (int p = 0; p < 4; p++)
        boff[p] = (uint32_t)(wn * 64 + p * 16 + ((lane >> 4) & 1) * 8 + (lane & 7)) * 80u +
                  ((lane >> 3) & 1) * 16u;

    uint32_t sAu = (uint32_t)__cvta_generic_to_shared(sA);
    uint32_t sBu = (uint32_t)__cvta_generic_to_shared(sB);

    int srow = tid >> 1;
    int c16  = (tid & 1) * 16;
    bool avalid = (nb + srow) < N_NODES;
    const __nv_bfloat16* abrow = Abf ? (Abf + (size_t)(nb + srow) * (2 * Kp)) : nullptr;
    const float* afrow = Af32 ? (Af32 + (size_t)(nb + srow) * 300) : nullptr;
    const __nv_bfloat16* brow = Wb + (size_t)srow * (2 * Kp);
    uint32_t sdst = (uint32_t)(srow * 80 + c16 * 2);

    uint4 Abuf[4];
    int nch = Kp / 32;

#define STAGE_B(KT, STG)                                                       \
    do {                                                                       \
        const __nv_bfloat16* _s = brow + (KT) + c16;                           \
        uint32_t _d = sBu + (uint32_t)(STG) * 2u * TILE_BYTES + sdst;          \
        CP16(_d, _s); CP16(_d + 16, _s + 8);                                   \
        const __nv_bfloat16* _sl = _s + Kp;                                    \
        uint32_t _dl = _d + TILE_BYTES;                                        \
        CP16(_dl, _sl); CP16(_dl + 16, _sl + 8);                               \
        CP_COMMIT();                                                           \
    } while (0)

#define LOAD_A(KT)                                                             \
    do {                                                                       \
        if (Abf) {                                                             \
            if (avalid) {                                                      \
                Abuf[0] = *(const uint4*)(abrow + (KT) + c16);                 \
                Abuf[1] = *(const uint4*)(abrow + (KT) + c16 + 8);             \
                Abuf[2] = *(const uint4*)(abrow + Kp + (KT) + c16);            \
                Abuf[3] = *(const uint4*)(abrow + Kp + (KT) + c16 + 8);        \
            } else {                                                           \
                Abuf[0] = Abuf[1] = Abuf[2] = Abuf[3] = make_uint4(0, 0, 0, 0);\
            }                                                                  \
        } else {                                                               \
            float v[16];                                                       \
            int col0 = (KT) + c16;                                             \
            if (avalid) {                                                      \
                _Pragma("unroll")                                              \
                for (int g = 0; g < 4; g++) {                                  \
                    int c = col0 + g * 4;                                      \
                    float4 f;                                                  \
                    if (c + 4 <= 300) f = *(const float4*)(afrow + c);         \
                    else f = make_float4(c + 0 < 300 ? afrow[c + 0] : 0.f,     \
                                         c + 1 < 300 ? afrow[c + 1] : 0.f,     \
                                         c + 2 < 300 ? afrow[c + 2] : 0.f,     \
                                         c + 3 < 300 ? afrow[c + 3] : 0.f);    \
                    v[g * 4 + 0] = f.x; v[g * 4 + 1] = f.y;                    \
                    v[g * 4 + 2] = f.z; v[g * 4 + 3] = f.w;                    \
                }                                                              \
            } else {                                                           \
                _Pragma("unroll")                                              \
                for (int j = 0; j < 16; j++) v[j] = 0.f;                       \
            }                                                                  \
            unsigned short hh[16], ll[16];                                     \
            _Pragma("unroll")                                                  \
            for (int j = 0; j < 16; j++) split_bf16(v[j], hh[j], ll[j]);       \
            Abuf[0] = *(uint4*)&hh[0]; Abuf[1] = *(uint4*)&hh[8];              \
            Abuf[2] = *(uint4*)&ll[0]; Abuf[3] = *(uint4*)&ll[8];              \
        }                                                                      \
    } while (0)

#define STORE_A(STG)                                                           \
    do {                                                                       \
        __nv_bfloat16* _h = sA + (size_t)(STG) * 2 * TILE_BF;                  \
        *(uint4*)((char*)_h + sdst)      = Abuf[0];                            \
        *(uint4*)((char*)_h + sdst + 16) = Abuf[1];                            \
        __nv_bfloat16* _l = _h + TILE_BF;                                      \
        *(uint4*)((char*)_l + sdst)      = Abuf[2];                            \
        *(uint4*)((char*)_l + sdst + 16) = Abuf[3];                            \
    } while (0)

    // prologue
    STAGE_B(0, 0);
    LOAD_A(0);
    STORE_A(0);
    CP_WAIT0();
    __syncthreads();

#pragma unroll 1
    for (int ch = 0; ch < nch; ch++) {
        int cur = ch & 1, nxt = cur ^ 1;
        if (ch + 1 < nch) {
            STAGE_B((ch + 1) * 32, nxt);
            LOAD_A((ch + 1) * 32);
        }
        uint32_t bAh = sAu + (uint32_t)cur * 2u * TILE_BYTES;
        uint32_t bAl = bAh + TILE_BYTES;
        uint32_t bBh = sBu + (uint32_t)cur * 2u * TILE_BYTES;
        uint32_t bBl = bBh + TILE_BYTES;
#pragma unroll
        for (int ks = 0; ks < 2; ks++) {
            uint32_t kb = ks * 32u;
            uint32_t ah[2][4], al[2][4];
            LDMX4(ah[0], bAh + aoff[0] + kb);
            LDMX4(ah[1], bAh + aoff[1] + kb);
            LDMX4(al[0], bAl + aoff[0] + kb);
            LDMX4(al[1], bAl + aoff[1] + kb);
#pragma unroll
            for (int p = 0; p < 4; p++) {
                uint32_t bh[4], bl[4];
                LDMX4(bh, bBh + boff[p] + kb);
#pragma unroll
                for (int t = 0; t < 2; t++) {
                    int nt = 2 * p + t;
                    MMA16816(acc[0][nt], ah[0], bh[2 * t], bh[2 * t + 1]);
                    MMA16816(acc[1][nt], ah[1], bh[2 * t], bh[2 * t + 1]);
                    MMA16816(acc[0][nt], al[0], bh[2 * t], bh[2 * t + 1]);
                    MMA16816(acc[1][nt], al[1], bh[2 * t], bh[2 * t + 1]);
                }
                LDMX4(bl, bBl + boff[p] + kb);
#pragma unroll
                for (int t = 0; t < 2; t++) {
                    int nt = 2 * p + t;
                    MMA16816(acc[0][nt], ah[0], bl[2 * t], bl[2 * t + 1]);
                    MMA16816(acc[1][nt], ah[1], bl[2 * t], bl[2 * t + 1]);
                }
            }
        }
        if (ch + 1 < nch) STORE_A(nxt);
        CP_WAIT0();
        __syncthreads();
    }

    // ---------------- epilogue ----------------
    int q = lane >> 2;
    int rchunk = lane & 3;

    if (mode == 0) {
#pragma unroll
        for (int mt = 0; mt < 2; mt++) {
            int lr0 = wm * 32 + mt * 16 + q;
            int r0 = nb + lr0, r1 = r0 + 8;
#pragma unroll
            for (int nt = 0; nt < 8; nt++) {
                int cb = wn * 64 + nt * 8 + 2 * rchunk;
                float b0 = s_bias[cb], b1 = s_bias[cb + 1];
                if (r0 < N_NODES) {
                    float2 e = *(const float2*)(emb + (size_t)(r0 + 1) * D + cb);
                    float v0 = acc[mt][nt][0] + b0;
                    float v1 = acc[mt][nt][1] + b1;
                    v0 = (v0 > 0.f) ? v0 : 0.1f * v0;
                    v1 = (v1 > 0.f) ? v1 : 0.1f * v1;
                    float2 o = make_float2(v0 + e.x, v1 + e.y);
                    *(float2*)(out + (size_t)r0 * D + cb) = o;
                }
                if (r1 < N_NODES) {
                    float2 e = *(const float2*)(emb + (size_t)(r1 + 1) * D + cb);
                    float v2 = acc[mt][nt][2] + b0;
                    float v3 = acc[mt][nt][3] + b1;
                    v2 = (v2 > 0.f) ? v2 : 0.1f * v2;
                    v3 = (v3 > 0.f) ? v3 : 0.1f * v3;
                    float2 o = make_float2(v2 + e.x, v3 + e.y);
                    *(float2*)(out + (size_t)r1 * D + cb) = o;
                }
            }
        }
    } else {
        float ssa[2] = {0.f, 0.f}, ssb[2] = {0.f, 0.f};
#pragma unroll
        for (int mt = 0; mt < 2; mt++) {
#pragma unroll
            for (int nt = 0; nt < 8; nt++) {
                int cb = wn * 64 + nt * 8 + 2 * rchunk;
                float b0 = s_bias[cb], b1 = s_bias[cb + 1];
                float v0 = acc[mt][nt][0] + b0;
                float v1 = acc[mt][nt][1] + b1;
                float v2 = acc[mt][nt][2] + b0;
                float v3 = acc[mt][nt][3] + b1;
                if (mode == 1) {
                    v0 = (v0 > 0.f) ? v0 : 0.1f * v0;
                    v1 = (v1 > 0.f) ? v1 : 0.1f * v1;
                    v2 = (v2 > 0.f) ? v2 : 0.1f * v2;
                    v3 = (v3 > 0.f) ? v3 : 0.1f * v3;
                }
                acc[mt][nt][0] = v0; acc[mt][nt][1] = v1;
                acc[mt][nt][2] = v2; acc[mt][nt][3] = v3;
                ssa[mt] += v0 * v0 + v1 * v1;
                ssb[mt] += v2 * v2 + v3 * v3;
            }
            ssa[mt] += __shfl_xor_sync(0xFFFFFFFFu, ssa[mt], 1);
            ssa[mt] += __shfl_xor_sync(0xFFFFFFFFu, ssa[mt], 2);
            ssb[mt] += __shfl_xor_sync(0xFFFFFFFFu, ssb[mt], 1);
            ssb[mt] += __shfl_xor_sync(0xFFFFFFFFu, ssb[mt], 2);
            if (rchunk == 0) {
                s_rs[wm * 32 + mt * 16 + q][wn]     = ssa[mt];
                s_rs[wm * 32 + mt * 16 + 8 + q][wn] = ssb[mt];
            }
        }
        __syncthreads();
#pragma unroll
        for (int mt = 0; mt < 2; mt++) {
            int lr0 = wm * 32 + mt * 16 + q;
            int r0 = nb + lr0, r1 = r0 + 8;
            float t0 = s_rs[lr0][0] + s_rs[lr0][1];
            float t1 = s_rs[lr0 + 8][0] + s_rs[lr0 + 8][1];
            float inv0 = 1.0f / fmaxf(sqrtf(t0), 1e-6f);
            float inv1 = 1.0f / fmaxf(sqrtf(t1), 1e-6f);
#pragma unroll
            for (int nt = 0; nt < 8; nt++) {
                int cb = wn * 64 + nt * 8 + 2 * rchunk;
                if (r0 < N_NODES) {
                    float2 o = make_float2(acc[mt][nt][0] * inv0,
                                           acc[mt][nt][1] * inv0);
                    *(float2*)(out + (size_t)r0 * D + cb) = o;
                }
                if (r1 < N_NODES) {
                    float2 o = make_float2(acc[mt][nt][2] * inv1,
                                           acc[mt][nt][3] * inv1);
                    *(float2*)(out + (size_t)r1 * D + cb) = o;
                }
            }
        }
    }
}

// ---------------------------------------------------------------------------
static cudaStream_t g_s2 = nullptr;
static cudaEvent_t  g_evFork = nullptr, g_evJoin = nullptr;

extern "C" void kernel_launch(void* const* d_in, const int* in_sizes, int n_in,
                              void* d_out, int out_size) {
    const float* node_emb = (const float*)d_in[0];
    const float* content  = (const float*)d_in[1];
    const float* proj_W   = (const float*)d_in[2];
    const float* proj_b   = (const float*)d_in[3];
    const float* W1       = (const float*)d_in[4];
    const float* b1       = (const float*)d_in[5];
    const float* W2       = (const float*)d_in[6];
    const float* b2       = (const float*)d_in[7];
    const int*   esrc     = (const int*)d_in[8];
    const int*   edst     = (const int*)d_in[9];
    int etot = in_sizes[8];
    float* out = (float*)d_out;

    // one-time setup on the (uncaptured) correctness call
    if (!g_s2) {
        cudaStreamCreateWithFlags(&g_s2, cudaStreamNonBlocking);
        cudaEventCreateWithFlags(&g_evFork, cudaEventDisableTiming);
        cudaEventCreateWithFlags(&g_evJoin, cudaEventDisableTiming);
        cudaFuncSetAttribute(k_gemm, cudaFuncAttributeMaxDynamicSharedMemorySize,
                             GEMM_SMEM);
    }

    float *h0, *h1;
    cudaGetSymbolAddress((void**)&h0, g_h0);
    cudaGetSymbolAddress((void**)&h1, g_h1);
    __nv_bfloat16 *xbf, *wmix, *w1, *w2;
    cudaGetSymbolAddress((void**)&xbf, g_xbf);
    cudaGetSymbolAddress((void**)&wmix, g_wmix);
    cudaGetSymbolAddress((void**)&w1, g_w1);
    cudaGetSymbolAddress((void**)&w2, g_w2);
    int* cnt;
    cudaGetSymbolAddress((void**)&cnt, g_cnt);

    int e_blocks  = (etot + 255) / 256;
    int gw_blocks = (N_NODES * 32 + 255) / 256;   // 1 warp per node
    int gemm_blocks = (N_NODES + 127) / 128;      // 391
    int prep_total = 128 * 40 + 2 * 128 * 32;

    // ---- fork: CSR build on side stream, concurrent with prep + mix GEMM ----
    cudaEventRecord(g_evFork, 0);
    cudaStreamWaitEvent(g_s2, g_evFork, 0);

    cudaMemsetAsync(cnt, 0, N_NODES * sizeof(int), g_s2);
    k_hist<<<e_blocks, 256, 0, g_s2>>>(edst, etot);
    k_scan<<<1, SCAN_T, 0, g_s2>>>(etot);
    k_fill<<<e_blocks, 256, 0, g_s2>>>(esrc, edst, etot);
    cudaEventRecord(g_evJoin, g_s2);

    // main stream: weight prep + mix GEMM (independent of CSR)
    k_prep_w_all<<<(prep_total + 255) / 256, 256>>>(proj_W, W1, W2);
    k_gemm<<<gemm_blocks, 256, GEMM_SMEM>>>(nullptr, content, 320, wmix, proj_b,
                                            node_emb, h0, 0);

    // join
    cudaStreamWaitEvent(0, g_evJoin, 0);

    // layer 1
    k_gather<<<gw_blocks, 256>>>(h0);
    k_gemm<<<gemm_blocks, 256, GEMM_SMEM>>>(xbf, nullptr, 256, w1, b1, nullptr,
                                            h1, 1);

    // layer 2
    k_gather<<<gw_blocks, 256>>>(h1);
    k_gemm<<<gemm_blocks, 256, GEMM_SMEM>>>(xbf, nullptr, 256, w2, b2, nullptr,
                                            out, 2);
}